// round 9
// baseline (speedup 1.0000x reference)
#include <cuda_runtime.h>
#include <cuda_bf16.h>
#include <cstdint>

// ============================================================================
// out[b,w,h,o] = W2 @ relu( patch(x)[p,144] x WF[144,128] + b1f ) + b2
// mma.sync m16n8k16 bf16, 2-term split, 3 cross-term MMAs.
// 512 threads: warp grid 4(M)x4(N), M32 x N32 per warp (min fragment traffic).
// Tail 128->16 GEMM on tensor cores, K split over 4 N-warps; partials summed
// in the store pass. cp.async double-buffered x prefetch.
// R9 fix: __syncthreads() before staging overlays the A region (WAR race).
// ============================================================================

#define NTHREADS 512
#define TILES_PER_BLOCK 4
#define NBLOCKS 1024

#define A_STRIDE_B 304                   // 152 bf16 per row
#define SB_BHI   0                       // [128][152] bf16
#define SB_BLO   38912
#define SB_AHI   77824                   // A hi (dead after GEMM -> out staging)
#define SB_ALO   116736
#define SB_X0    155648                  // [16][3][132] f32 (buf 0)
#define SB_X1    180992                  // (buf 1)
#define SB_W2H   206336                  // [16][152] bf16
#define SB_W2L   211200
#define SB_B1    216064                  // 128 f32
#define SB_B2    216576                  // 16 f32
#define SMEM_BYTES 216640
// output staging: 4 partial buffers x 10240 B = 40960 B overlaying A region

__device__ __nv_bfloat16 g_Bhi[128 * 152];
__device__ __nv_bfloat16 g_Blo[128 * 152];
__device__ __nv_bfloat16 g_W2h[16 * 152];
__device__ __nv_bfloat16 g_W2l[16 * 152];
__device__ float g_B1f[128];

// ---------------------------------------------------------------------------
__device__ __forceinline__ uint32_t smem_u32(const void* p) {
    uint32_t a;
    asm("{ .reg .u64 t; cvta.to.shared.u64 t, %1; cvt.u32.u64 %0, t; }" : "=r"(a) : "l"(p));
    return a;
}
__device__ __forceinline__ void ldsm_x4(uint32_t* r, uint32_t addr) {
    asm volatile("ldmatrix.sync.aligned.m8n8.x4.shared.b16 {%0,%1,%2,%3}, [%4];"
                 : "=r"(r[0]), "=r"(r[1]), "=r"(r[2]), "=r"(r[3]) : "r"(addr));
}
__device__ __forceinline__ void mma_bf16(float* c, const uint32_t* a, const uint32_t* b) {
    asm volatile("mma.sync.aligned.m16n8k16.row.col.f32.bf16.bf16.f32 "
                 "{%0,%1,%2,%3}, {%4,%5,%6,%7}, {%8,%9}, {%0,%1,%2,%3};"
                 : "+f"(c[0]), "+f"(c[1]), "+f"(c[2]), "+f"(c[3])
                 : "r"(a[0]), "r"(a[1]), "r"(a[2]), "r"(a[3]), "r"(b[0]), "r"(b[1]));
}
__device__ __forceinline__ uint32_t cvt_bf16x2(float hi, float lo) {
    uint32_t r;
    asm("cvt.rn.bf16x2.f32 %0, %1, %2;" : "=r"(r) : "f"(hi), "f"(lo));
    return r;
}
#define CP_COMMIT() asm volatile("cp.async.commit_group;" ::: "memory")
#define CP_WAIT1()  asm volatile("cp.async.wait_group 1;" ::: "memory")

__device__ __forceinline__ void prefetch_x(const float* __restrict__ x, int tile,
                                           uint32_t xbuf, int tid) {
    const int b = tile >> 7, h = tile & 127;
    for (int idx = tid; idx < 16 * 3 * 132; idx += NTHREADS) {
        int c = idx / 396;
        int rem = idx - c * 396;
        int r = rem / 132;
        int ww = rem - r * 132;
        int hh = h + r - 1, wg = ww - 1;
        bool ok = ((unsigned)hh < 128u) && ((unsigned)wg < 128u);
        int hc = ok ? hh : 0, wc = ok ? wg : 0;
        const float* g = x + ((b * 16 + c) << 14) + (hc << 7) + wc;
        int sz = ok ? 4 : 0;
        asm volatile("cp.async.ca.shared.global [%0], [%1], 4, %2;"
                     :: "r"(xbuf + (uint32_t)idx * 4), "l"(g), "r"(sz) : "memory");
    }
}

// ---------------------------------------------------------------------------
__global__ void prep_kernel(const float* __restrict__ Wx,
                            const float* __restrict__ Wy,
                            const float* __restrict__ W1,
                            const float* __restrict__ b1,
                            const float* __restrict__ bx,
                            const float* __restrict__ by,
                            const float* __restrict__ W2) {
    int idx = blockIdx.x * blockDim.x + threadIdx.x;
    if (idx < 128 * 144) {
        int m = idx / 144, k = idx - m * 144;
        int i = k / 9, kk = k - i * 9;
        const float* w1r = W1 + m * 48;
        float f = 0.f;
#pragma unroll
        for (int o = 0; o < 16; ++o) {
            f += w1r[o]      * Wx[(o * 16 + i) * 9 + kk];
            f += w1r[16 + o] * Wy[(o * 16 + i) * 9 + kk];
        }
        if (kk == 4) f += w1r[32 + i];
        __nv_bfloat16 hi = __float2bfloat16(f);
        __nv_bfloat16 lo = __float2bfloat16(f - __bfloat162float(hi));
        g_Bhi[m * 152 + k] = hi;
        g_Blo[m * 152 + k] = lo;
    }
    if (idx < 2048) {
        int o = idx >> 7, m = idx & 127;
        float f = W2[o * 128 + m];
        __nv_bfloat16 hi = __float2bfloat16(f);
        __nv_bfloat16 lo = __float2bfloat16(f - __bfloat162float(hi));
        g_W2h[o * 152 + m] = hi;
        g_W2l[o * 152 + m] = lo;
    }
    if (idx < 128) {
        float s = b1[idx];
        const float* w1r = W1 + idx * 48;
#pragma unroll
        for (int o = 0; o < 16; ++o) s += w1r[o] * bx[o] + w1r[16 + o] * by[o];
        g_B1f[idx] = s;
    }
}

// ---------------------------------------------------------------------------
__global__ __launch_bounds__(NTHREADS, 1)
void nca_mma_kernel(const float* __restrict__ x,
                    const float* __restrict__ b2g,
                    float* __restrict__ out) {
    extern __shared__ char sm[];
    float* smf = (float*)sm;
    const uint32_t smem_base = smem_u32(sm);
    const int tid = threadIdx.x;
    const int wid = tid >> 5;
    const int lane = tid & 31;
    const int q = lane & 3;
    const int mw = wid & 3;    // pixels [mw*32, +32)
    const int nw = wid >> 2;   // hidden [nw*32, +32)
    const int tile_base = blockIdx.x * TILES_PER_BLOCK;

    // ---- stage persistent weights ----
    {
        const uint4* gh = (const uint4*)g_Bhi;
        const uint4* gl = (const uint4*)g_Blo;
        uint4* shh = (uint4*)(sm + SB_BHI);
        uint4* shl = (uint4*)(sm + SB_BLO);
        for (int i = tid; i < 2432; i += NTHREADS) { shh[i] = gh[i]; shl[i] = gl[i]; }
        uint4* w2h = (uint4*)(sm + SB_W2H);
        uint4* w2l = (uint4*)(sm + SB_W2L);
        const uint4* gw2h = (const uint4*)g_W2h;
        const uint4* gw2l = (const uint4*)g_W2l;
        for (int i = tid; i < 304; i += NTHREADS) { w2h[i] = gw2h[i]; w2l[i] = gw2l[i]; }
        if (tid < 128) smf[SB_B1 / 4 + tid] = g_B1f[tid];
        if (tid < 16)  smf[SB_B2 / 4 + tid] = b2g[tid];
    }
    prefetch_x(x, tile_base, smem_base + SB_X0, tid);
    CP_COMMIT();
    __syncthreads();

    // ---- hoist bias fragments (4 n8 groups within this warp's 32 hidden) ----
    float bini[4][2];
#pragma unroll
    for (int g = 0; g < 4; ++g) {
        bini[g][0] = smf[SB_B1 / 4 + nw * 32 + g * 8 + q * 2];
        bini[g][1] = smf[SB_B1 / 4 + nw * 32 + g * 8 + q * 2 + 1];
    }
    float b2i[2][2];
#pragma unroll
    for (int jj = 0; jj < 2; ++jj) {
        b2i[jj][0] = (nw == 0) ? smf[SB_B2 / 4 + jj * 8 + q * 2] : 0.f;
        b2i[jj][1] = (nw == 0) ? smf[SB_B2 / 4 + jj * 8 + q * 2 + 1] : 0.f;
    }

    const int p_build = tid & 127;
    const int s_build = tid >> 7;          // k-slice: k in [36s, 36s+36)

    const uint32_t a_addr0 = smem_base + SB_AHI +
        (uint32_t)(mw * 32 + (lane & 7) + ((lane >> 3) & 1) * 8) * A_STRIDE_B +
        (uint32_t)((lane >> 4) * 16);
    const uint32_t b_addr0 = smem_base + SB_BHI +
        (uint32_t)(nw * 32 + (lane & 7) + (lane >> 4) * 8) * A_STRIDE_B +
        (uint32_t)(((lane >> 3) & 1) * 16);
    const uint32_t w2_addr0 = smem_base + SB_W2H +
        (uint32_t)((lane & 7) + (lane >> 4) * 8) * A_STRIDE_B +
        (uint32_t)(((lane >> 3) & 1) * 16) + (uint32_t)(nw * 64);

#pragma unroll
    for (int j = 0; j < TILES_PER_BLOCK; ++j) {
        const int tile = tile_base + j;
        const int b = tile >> 7;
        const int h = tile & 127;
        const uint32_t xcur_off = (j & 1) ? SB_X1 : SB_X0;
        const uint32_t xnext_off = (j & 1) ? SB_X0 : SB_X1;

        {
            int tn = tile + 1;
            if (tn > NBLOCKS * TILES_PER_BLOCK - 1) tn = NBLOCKS * TILES_PER_BLOCK - 1;
            prefetch_x(x, tn, smem_base + xnext_off, tid);
            CP_COMMIT();
        }
        CP_WAIT1();
        __syncthreads();

        // ---- build A_hi/A_lo [p][k] bf16; thread = (pixel, 36-k slice) ----
        {
            const float* xp = smf + xcur_off / 4 + p_build;
            char* ahp = sm + SB_AHI + p_build * A_STRIDE_B + 72 * s_build;
            char* alp = sm + SB_ALO + p_build * A_STRIDE_B + 72 * s_build;
#pragma unroll
            for (int u = 0; u < 9; ++u) {
                uint32_t h2[2], l2[2];
#pragma unroll
                for (int e = 0; e < 2; ++e) {
                    int d0 = u * 4 + e * 2, d1 = d0 + 1;
                    int i0 = 4 * s_build + d0 / 9, t0 = d0 % 9;
                    int i1 = 4 * s_build + d1 / 9, t1 = d1 % 9;
                    float v0 = xp[i0 * 396 + (t0 / 3) * 132 + (t0 % 3)];
                    float v1 = xp[i1 * 396 + (t1 / 3) * 132 + (t1 % 3)];
                    uint32_t hp = cvt_bf16x2(v1, v0);
                    float f0 = __uint_as_float(hp << 16);
                    float f1 = __uint_as_float(hp & 0xFFFF0000u);
                    h2[e] = hp;
                    l2[e] = cvt_bf16x2(v1 - f1, v0 - f0);
                }
                *(uint2*)(ahp + u * 8) = make_uint2(h2[0], h2[1]);
                *(uint2*)(alp + u * 8) = make_uint2(l2[0], l2[1]);
            }
        }
        __syncthreads();

        // ---- main GEMM: M32 x N32 x K144 per warp, acc init = b1 ----
        float acc[2][4][4];
#pragma unroll
        for (int mt = 0; mt < 2; ++mt)
#pragma unroll
            for (int g = 0; g < 4; ++g) {
                acc[mt][g][0] = bini[g][0]; acc[mt][g][1] = bini[g][1];
                acc[mt][g][2] = bini[g][0]; acc[mt][g][3] = bini[g][1];
            }

#pragma unroll
        for (int ks = 0; ks < 9; ++ks) {
            const uint32_t kb = (uint32_t)(ks * 32);
            uint32_t ah[2][4], al[2][4];
#pragma unroll
            for (int mt = 0; mt < 2; ++mt) {
                uint32_t aa = a_addr0 + (uint32_t)(mt * 16) * A_STRIDE_B + kb;
                ldsm_x4(ah[mt], aa);
                ldsm_x4(al[mt], aa + (SB_ALO - SB_AHI));
            }
#pragma unroll
            for (int g2 = 0; g2 < 2; ++g2) {
                uint32_t bh[4], bl[4];
                uint32_t ba = b_addr0 + (uint32_t)(g2 * 16) * A_STRIDE_B + kb;
                ldsm_x4(bh, ba);
                ldsm_x4(bl, ba + (SB_BLO - SB_BHI));
#pragma unroll
                for (int mt = 0; mt < 2; ++mt) {
                    mma_bf16(acc[mt][2 * g2],     ah[mt], &bh[0]);
                    mma_bf16(acc[mt][2 * g2 + 1], ah[mt], &bh[2]);
                    mma_bf16(acc[mt][2 * g2],     al[mt], &bh[0]);
                    mma_bf16(acc[mt][2 * g2 + 1], al[mt], &bh[2]);
                    mma_bf16(acc[mt][2 * g2],     ah[mt], &bl[0]);
                    mma_bf16(acc[mt][2 * g2 + 1], ah[mt], &bl[2]);
                }
            }
        }

        // ---- tail GEMM over this warp's K=32 hidden slice ----
        float oacc[2][2][4];
#pragma unroll
        for (int mt = 0; mt < 2; ++mt)
#pragma unroll
            for (int jj = 0; jj < 2; ++jj) {
                oacc[mt][jj][0] = b2i[jj][0]; oacc[mt][jj][1] = b2i[jj][1];
                oacc[mt][jj][2] = b2i[jj][0]; oacc[mt][jj][3] = b2i[jj][1];
            }

#pragma unroll
        for (int kt = 0; kt < 2; ++kt) {
            uint32_t wh[4], wl[4];
            uint32_t waddr = w2_addr0 + (uint32_t)(kt * 32);
            ldsm_x4(wh, waddr);
            ldsm_x4(wl, waddr + (SB_W2L - SB_W2H));
#pragma unroll
            for (int mt = 0; mt < 2; ++mt) {
                float y0 = fmaxf(acc[mt][2 * kt][0], 0.f),     y1 = fmaxf(acc[mt][2 * kt][1], 0.f);
                float y2 = fmaxf(acc[mt][2 * kt][2], 0.f),     y3 = fmaxf(acc[mt][2 * kt][3], 0.f);
                float z0 = fmaxf(acc[mt][2 * kt + 1][0], 0.f), z1 = fmaxf(acc[mt][2 * kt + 1][1], 0.f);
                float z2 = fmaxf(acc[mt][2 * kt + 1][2], 0.f), z3 = fmaxf(acc[mt][2 * kt + 1][3], 0.f);
                uint32_t ah2[4], al2[4];
                ah2[0] = cvt_bf16x2(y1, y0);
                ah2[1] = cvt_bf16x2(y3, y2);
                ah2[2] = cvt_bf16x2(z1, z0);
                ah2[3] = cvt_bf16x2(z3, z2);
                al2[0] = cvt_bf16x2(y1 - __uint_as_float(ah2[0] & 0xFFFF0000u),
                                    y0 - __uint_as_float(ah2[0] << 16));
                al2[1] = cvt_bf16x2(y3 - __uint_as_float(ah2[1] & 0xFFFF0000u),
                                    y2 - __uint_as_float(ah2[1] << 16));
                al2[2] = cvt_bf16x2(z1 - __uint_as_float(ah2[2] & 0xFFFF0000u),
                                    z0 - __uint_as_float(ah2[2] << 16));
                al2[3] = cvt_bf16x2(z3 - __uint_as_float(ah2[3] & 0xFFFF0000u),
                                    z2 - __uint_as_float(ah2[3] << 16));
                mma_bf16(oacc[mt][0], ah2, &wh[0]);
                mma_bf16(oacc[mt][1], ah2, &wh[2]);
                mma_bf16(oacc[mt][0], al2, &wh[0]);
                mma_bf16(oacc[mt][1], al2, &wh[2]);
                mma_bf16(oacc[mt][0], ah2, &wl[0]);
                mma_bf16(oacc[mt][1], ah2, &wl[2]);
            }
        }

        // ---- all warps' A reads complete BEFORE staging overlays A ----
        __syncthreads();

        // ---- stage partials into dead A region: 4 buffers by nw ----
        {
            float* obuf = smf + SB_AHI / 4 + nw * 2560;
#pragma unroll
            for (int mt = 0; mt < 2; ++mt) {
                int p0 = mw * 32 + mt * 16 + (lane >> 2);
                float* s0 = obuf + p0 * 20;
                float* s1 = obuf + (p0 + 8) * 20;
                *(float2*)(s0 + 2 * q)     = make_float2(oacc[mt][0][0], oacc[mt][0][1]);
                *(float2*)(s0 + 8 + 2 * q) = make_float2(oacc[mt][1][0], oacc[mt][1][1]);
                *(float2*)(s1 + 2 * q)     = make_float2(oacc[mt][0][2], oacc[mt][0][3]);
                *(float2*)(s1 + 8 + 2 * q) = make_float2(oacc[mt][1][2], oacc[mt][1][3]);
            }
        }
        __syncthreads();

        // ---- sum 4 partials + coalesced store (512 float4, 1 pass) ----
        {
            const long obase = ((long)b << 18) + ((long)h << 4);
            const float* o0 = smf + SB_AHI / 4;
            int p = tid >> 2, c4 = (tid & 3) * 4;      // p in [0,128)
            float4 v0 = *(const float4*)(o0 + p * 20 + c4);
            float4 v1 = *(const float4*)(o0 + 2560 + p * 20 + c4);
            float4 v2 = *(const float4*)(o0 + 5120 + p * 20 + c4);
            float4 v3 = *(const float4*)(o0 + 7680 + p * 20 + c4);
            float4 v = make_float4(v0.x + v1.x + v2.x + v3.x,
                                   v0.y + v1.y + v2.y + v3.y,
                                   v0.z + v1.z + v2.z + v3.z,
                                   v0.w + v1.w + v2.w + v3.w);
            *(float4*)(out + obase + ((long)p << 11) + c4) = v;
        }
        __syncthreads();   // staging reads done before next A-build overwrites
    }
}

extern "C" void kernel_launch(void* const* d_in, const int* in_sizes, int n_in,
                              void* d_out, int out_size) {
    const float* x  = (const float*)d_in[0];
    const float* Wx = (const float*)d_in[1];
    const float* bx = (const float*)d_in[2];
    const float* Wy = (const float*)d_in[3];
    const float* by = (const float*)d_in[4];
    const float* W1 = (const float*)d_in[5];
    const float* b1 = (const float*)d_in[6];
    const float* W2 = (const float*)d_in[7];
    const float* b2 = (const float*)d_in[8];
    float* out = (float*)d_out;

    prep_kernel<<<72, 256>>>(Wx, Wy, W1, b1, bx, by, W2);

    cudaFuncSetAttribute(nca_mma_kernel,
                         cudaFuncAttributeMaxDynamicSharedMemorySize, SMEM_BYTES);
    nca_mma_kernel<<<NBLOCKS, NTHREADS, SMEM_BYTES>>>(x, b2, out);
}

// round 10
// speedup vs baseline: 1.2357x; 1.2357x over previous
#include <cuda_runtime.h>
#include <cuda_bf16.h>
#include <cstdint>

// ============================================================================
// out[b,w,h,o] = W2 @ relu( patch(x)[p,144] x WF[144,128] + b1f ) + b2
// mma.sync m16n8k16 bf16, 2-term split, 3 cross-term MMAs.
// k-order = (kh,kw,i); kw folded into ldmatrix ROW offset (pixel shift), so
// the im2col matrix is never built: A-tile = channel-last x rows (bf16 hi/lo,
// precomputed in GMEM), cp.async'ed straight into SMEM, double-buffered.
// 512 threads, warp grid 4(M)x4(N); tensor-core tail; dedicated staging.
// ============================================================================

#define NTHREADS 512
#define TILES_PER_BLOCK 4
#define NBLOCKS 1024

#define AT_STRIDE 112                    // 48 bf16 cols padded to 112B
#define SB_BHI   0                       // B_hi [128][152] bf16
#define SB_BLO   38912
#define SB_AT0H  77824                   // Atilde buf0 hi: 130 x 112B
#define SB_AT0L  92384
#define SB_AT1H  106944
#define SB_AT1L  121504
#define SB_W2H   136064                  // [16][152] bf16
#define SB_W2L   140928
#define SB_B1    145792                  // 128 f32
#define SB_B2    146304                  // 16 f32
#define SB_OUT   146368                  // 4 x [128][20] f32 partials
#define SMEM_BYTES 187328
#define AT_LO_OFF 14560                  // hi -> lo delta (both buffers)

__device__ __nv_bfloat16 g_Bhi[128 * 152];
__device__ __nv_bfloat16 g_Blo[128 * 152];
__device__ __nv_bfloat16 g_W2h[16 * 152];
__device__ __nv_bfloat16 g_W2l[16 * 152];
__device__ float g_B1f[128];
// channel-last bf16 split of x: [b][h][w][c]
__device__ __nv_bfloat16 g_xTh[32 * 128 * 128 * 16];
__device__ __nv_bfloat16 g_xTl[32 * 128 * 128 * 16];

// ---------------------------------------------------------------------------
__device__ __forceinline__ uint32_t smem_u32(const void* p) {
    uint32_t a;
    asm("{ .reg .u64 t; cvta.to.shared.u64 t, %1; cvt.u32.u64 %0, t; }" : "=r"(a) : "l"(p));
    return a;
}
__device__ __forceinline__ void ldsm_x4(uint32_t* r, uint32_t addr) {
    asm volatile("ldmatrix.sync.aligned.m8n8.x4.shared.b16 {%0,%1,%2,%3}, [%4];"
                 : "=r"(r[0]), "=r"(r[1]), "=r"(r[2]), "=r"(r[3]) : "r"(addr));
}
__device__ __forceinline__ void mma_bf16(float* c, const uint32_t* a, const uint32_t* b) {
    asm volatile("mma.sync.aligned.m16n8k16.row.col.f32.bf16.bf16.f32 "
                 "{%0,%1,%2,%3}, {%4,%5,%6,%7}, {%8,%9}, {%0,%1,%2,%3};"
                 : "+f"(c[0]), "+f"(c[1]), "+f"(c[2]), "+f"(c[3])
                 : "r"(a[0]), "r"(a[1]), "r"(a[2]), "r"(a[3]), "r"(b[0]), "r"(b[1]));
}
__device__ __forceinline__ uint32_t cvt_bf16x2(float hi, float lo) {
    uint32_t r;
    asm("cvt.rn.bf16x2.f32 %0, %1, %2;" : "=r"(r) : "f"(hi), "f"(lo));
    return r;
}
#define CP_COMMIT() asm volatile("cp.async.commit_group;" ::: "memory")
#define CP_WAIT1()  asm volatile("cp.async.wait_group 1;" ::: "memory")

// prefetch Atilde (130 rows x 3 kh-chunks x 32B, hi+lo) for tile into at_hi
__device__ __forceinline__ void prefetch_at(int tile, uint32_t at_hi, int tid) {
    const int b = tile >> 7, h = tile & 127;
#pragma unroll
    for (int it = 0; it < 2; ++it) {
        int idx = tid + it * NTHREADS;
        if (idx >= 780) break;
        int prec = idx / 390;
        int rem = idx - prec * 390;
        int kh = rem / 130;
        int pp = rem - kh * 130;
        int hh = h + kh - 1, w = pp - 1;
        bool ok = ((unsigned)hh < 128u) && ((unsigned)w < 128u);
        const __nv_bfloat16* base = prec ? g_xTl : g_xTh;
        const __nv_bfloat16* src = base +
            ((((long)(b << 7) + (ok ? hh : 0)) << 7) + (ok ? w : 0)) * 16;
        uint32_t dst = at_hi + (uint32_t)prec * AT_LO_OFF +
                       (uint32_t)pp * AT_STRIDE + (uint32_t)kh * 32;
        int sz = ok ? 16 : 0;
        asm volatile("cp.async.ca.shared.global [%0], [%1], 16, %2;"
                     :: "r"(dst), "l"(src), "r"(sz) : "memory");
        asm volatile("cp.async.ca.shared.global [%0], [%1], 16, %2;"
                     :: "r"(dst + 16), "l"(src + 8), "r"(sz) : "memory");
    }
}

// ---------------------------------------------------------------------------
// prep 1: fused weights (k-order (kh,kw,i)), W2 split, fused bias
// ---------------------------------------------------------------------------
__global__ void prep_w_kernel(const float* __restrict__ Wx,
                              const float* __restrict__ Wy,
                              const float* __restrict__ W1,
                              const float* __restrict__ b1,
                              const float* __restrict__ bx,
                              const float* __restrict__ by,
                              const float* __restrict__ W2) {
    int idx = blockIdx.x * blockDim.x + threadIdx.x;
    if (idx < 128 * 144) {
        int m = idx / 144, k = idx - m * 144;
        int kh = k / 48, kw = (k % 48) / 16, i = k & 15;
        int kk = kh * 3 + kw;
        const float* w1r = W1 + m * 48;
        float f = 0.f;
#pragma unroll
        for (int o = 0; o < 16; ++o) {
            f += w1r[o]      * Wx[(o * 16 + i) * 9 + kk];
            f += w1r[16 + o] * Wy[(o * 16 + i) * 9 + kk];
        }
        if (kk == 4) f += w1r[32 + i];
        __nv_bfloat16 hi = __float2bfloat16(f);
        __nv_bfloat16 lo = __float2bfloat16(f - __bfloat162float(hi));
        g_Bhi[m * 152 + k] = hi;
        g_Blo[m * 152 + k] = lo;
    }
    if (idx < 2048) {
        int o = idx >> 7, m = idx & 127;
        float f = W2[o * 128 + m];
        __nv_bfloat16 hi = __float2bfloat16(f);
        __nv_bfloat16 lo = __float2bfloat16(f - __bfloat162float(hi));
        g_W2h[o * 152 + m] = hi;
        g_W2l[o * 152 + m] = lo;
    }
    if (idx < 128) {
        float s = b1[idx];
        const float* w1r = W1 + idx * 48;
#pragma unroll
        for (int o = 0; o < 16; ++o) s += w1r[o] * bx[o] + w1r[16 + o] * by[o];
        g_B1f[idx] = s;
    }
}

// ---------------------------------------------------------------------------
// prep 2: transpose x to channel-last + bf16 hi/lo split. block = (b,h) row.
// ---------------------------------------------------------------------------
__global__ void prep_t_kernel(const float* __restrict__ x) {
    __shared__ float s[16 * 132];
    const int bid = blockIdx.x;          // 4096 = 32 b x 128 h
    const int b = bid >> 7, h = bid & 127;
    const int tid = threadIdx.x;         // 256
#pragma unroll
    for (int t = tid; t < 2048; t += 256) {
        int c = t >> 7, w = t & 127;
        s[c * 132 + w] = x[((b * 16 + c) << 14) + (h << 7) + w];
    }
    __syncthreads();
#pragma unroll
    for (int t = tid; t < 2048; t += 256) {
        int w = t >> 4, c = t & 15;
        float v = s[c * 132 + w];
        __nv_bfloat16 hi = __float2bfloat16(v);
        __nv_bfloat16 lo = __float2bfloat16(v - __bfloat162float(hi));
        long off = ((((long)(b << 7) + h) << 7) + w) * 16 + c;
        g_xTh[off] = hi;
        g_xTl[off] = lo;
    }
}

// ---------------------------------------------------------------------------
__global__ __launch_bounds__(NTHREADS, 1)
void nca_mma_kernel(const float* __restrict__ b2g,
                    float* __restrict__ out) {
    extern __shared__ char sm[];
    float* smf = (float*)sm;
    const uint32_t smem_base = smem_u32(sm);
    const int tid = threadIdx.x;
    const int wid = tid >> 5;
    const int lane = tid & 31;
    const int q = lane & 3;
    const int mw = wid & 3;    // pixels [mw*32, +32)
    const int nw = wid >> 2;   // hidden [nw*32, +32)
    const int tile_base = blockIdx.x * TILES_PER_BLOCK;

    // ---- stage persistent weights ----
    {
        const uint4* gh = (const uint4*)g_Bhi;
        const uint4* gl = (const uint4*)g_Blo;
        uint4* shh = (uint4*)(sm + SB_BHI);
        uint4* shl = (uint4*)(sm + SB_BLO);
        for (int i = tid; i < 2432; i += NTHREADS) { shh[i] = gh[i]; shl[i] = gl[i]; }
        uint4* w2h = (uint4*)(sm + SB_W2H);
        uint4* w2l = (uint4*)(sm + SB_W2L);
        const uint4* gw2h = (const uint4*)g_W2h;
        const uint4* gw2l = (const uint4*)g_W2l;
        for (int i = tid; i < 304; i += NTHREADS) { w2h[i] = gw2h[i]; w2l[i] = gw2l[i]; }
        if (tid < 128) smf[SB_B1 / 4 + tid] = g_B1f[tid];
        if (tid < 16)  smf[SB_B2 / 4 + tid] = b2g[tid];
    }
    prefetch_at(tile_base, smem_base + SB_AT0H, tid);
    CP_COMMIT();
    __syncthreads();

    // ---- hoist bias fragments ----
    float bini[4][2];
#pragma unroll
    for (int g = 0; g < 4; ++g) {
        bini[g][0] = smf[SB_B1 / 4 + nw * 32 + g * 8 + q * 2];
        bini[g][1] = smf[SB_B1 / 4 + nw * 32 + g * 8 + q * 2 + 1];
    }
    float b2i[2][2];
#pragma unroll
    for (int jj = 0; jj < 2; ++jj) {
        b2i[jj][0] = (nw == 0) ? smf[SB_B2 / 4 + jj * 8 + q * 2] : 0.f;
        b2i[jj][1] = (nw == 0) ? smf[SB_B2 / 4 + jj * 8 + q * 2 + 1] : 0.f;
    }

    // ldsm address components
    const uint32_t a_row_off =
        (uint32_t)(mw * 32 + (lane & 7) + ((lane >> 3) & 1) * 8) * AT_STRIDE +
        (uint32_t)((lane >> 4) * 16);
    const uint32_t b_addr0 = smem_base + SB_BHI +
        (uint32_t)(nw * 32 + (lane & 7) + (lane >> 4) * 8) * 304 +
        (uint32_t)(((lane >> 3) & 1) * 16);
    const uint32_t w2_addr0 = smem_base + SB_W2H +
        (uint32_t)((lane & 7) + (lane >> 4) * 8) * 304 +
        (uint32_t)(((lane >> 3) & 1) * 16) + (uint32_t)(nw * 64);

#pragma unroll
    for (int j = 0; j < TILES_PER_BLOCK; ++j) {
        const int tile = tile_base + j;
        const int b = tile >> 7;
        const int h = tile & 127;
        const uint32_t at_cur = smem_base + ((j & 1) ? SB_AT1H : SB_AT0H);
        const uint32_t at_nxt = smem_base + ((j & 1) ? SB_AT0H : SB_AT1H);

        {
            int tn = tile + 1;
            if (tn > NBLOCKS * TILES_PER_BLOCK - 1) tn = NBLOCKS * TILES_PER_BLOCK - 1;
            prefetch_at(tn, at_nxt, tid);
            CP_COMMIT();
        }
        CP_WAIT1();
        __syncthreads();   // Atilde(j) visible to all warps; orders prev store-pass too

        // ---- main GEMM: M32 x N32 x K144 per warp, acc init = b1 ----
        float acc[2][4][4];
#pragma unroll
        for (int mt = 0; mt < 2; ++mt)
#pragma unroll
            for (int g = 0; g < 4; ++g) {
                acc[mt][g][0] = bini[g][0]; acc[mt][g][1] = bini[g][1];
                acc[mt][g][2] = bini[g][0]; acc[mt][g][3] = bini[g][1];
            }

#pragma unroll
        for (int ks = 0; ks < 9; ++ks) {
            const int kh = ks / 3, kw = ks - 3 * kh;
            const uint32_t ab = at_cur + a_row_off +
                (uint32_t)(kw * AT_STRIDE + kh * 32);
            uint32_t ah[2][4], al[2][4];
#pragma unroll
            for (int mt = 0; mt < 2; ++mt) {
                uint32_t aa = ab + (uint32_t)(mt * 16) * AT_STRIDE;
                ldsm_x4(ah[mt], aa);
                ldsm_x4(al[mt], aa + AT_LO_OFF);
            }
            const uint32_t kb = (uint32_t)(ks * 32);
#pragma unroll
            for (int g2 = 0; g2 < 2; ++g2) {
                uint32_t bh[4], bl[4];
                uint32_t ba = b_addr0 + (uint32_t)(g2 * 16) * 304 + kb;
                ldsm_x4(bh, ba);
                ldsm_x4(bl, ba + (SB_BLO - SB_BHI));
#pragma unroll
                for (int mt = 0; mt < 2; ++mt) {
                    mma_bf16(acc[mt][2 * g2],     ah[mt], &bh[0]);
                    mma_bf16(acc[mt][2 * g2 + 1], ah[mt], &bh[2]);
                    mma_bf16(acc[mt][2 * g2],     al[mt], &bh[0]);
                    mma_bf16(acc[mt][2 * g2 + 1], al[mt], &bh[2]);
                    mma_bf16(acc[mt][2 * g2],     ah[mt], &bl[0]);
                    mma_bf16(acc[mt][2 * g2 + 1], ah[mt], &bl[2]);
                }
            }
        }

        // ---- tail GEMM over this warp's K=32 hidden slice ----
        float oacc[2][2][4];
#pragma unroll
        for (int mt = 0; mt < 2; ++mt)
#pragma unroll
            for (int jj = 0; jj < 2; ++jj) {
                oacc[mt][jj][0] = b2i[jj][0]; oacc[mt][jj][1] = b2i[jj][1];
                oacc[mt][jj][2] = b2i[jj][0]; oacc[mt][jj][3] = b2i[jj][1];
            }

#pragma unroll
        for (int kt = 0; kt < 2; ++kt) {
            uint32_t wh[4], wl[4];
            uint32_t waddr = w2_addr0 + (uint32_t)(kt * 32);
            ldsm_x4(wh, waddr);
            ldsm_x4(wl, waddr + (SB_W2L - SB_W2H));
#pragma unroll
            for (int mt = 0; mt < 2; ++mt) {
                float y0 = fmaxf(acc[mt][2 * kt][0], 0.f),     y1 = fmaxf(acc[mt][2 * kt][1], 0.f);
                float y2 = fmaxf(acc[mt][2 * kt][2], 0.f),     y3 = fmaxf(acc[mt][2 * kt][3], 0.f);
                float z0 = fmaxf(acc[mt][2 * kt + 1][0], 0.f), z1 = fmaxf(acc[mt][2 * kt + 1][1], 0.f);
                float z2 = fmaxf(acc[mt][2 * kt + 1][2], 0.f), z3 = fmaxf(acc[mt][2 * kt + 1][3], 0.f);
                uint32_t ah2[4], al2[4];
                ah2[0] = cvt_bf16x2(y1, y0);
                ah2[1] = cvt_bf16x2(y3, y2);
                ah2[2] = cvt_bf16x2(z1, z0);
                ah2[3] = cvt_bf16x2(z3, z2);
                al2[0] = cvt_bf16x2(y1 - __uint_as_float(ah2[0] & 0xFFFF0000u),
                                    y0 - __uint_as_float(ah2[0] << 16));
                al2[1] = cvt_bf16x2(y3 - __uint_as_float(ah2[1] & 0xFFFF0000u),
                                    y2 - __uint_as_float(ah2[1] << 16));
                al2[2] = cvt_bf16x2(z1 - __uint_as_float(ah2[2] & 0xFFFF0000u),
                                    z0 - __uint_as_float(ah2[2] << 16));
                al2[3] = cvt_bf16x2(z3 - __uint_as_float(ah2[3] & 0xFFFF0000u),
                                    z2 - __uint_as_float(ah2[3] << 16));
                mma_bf16(oacc[mt][0], ah2, &wh[0]);
                mma_bf16(oacc[mt][1], ah2, &wh[2]);
                mma_bf16(oacc[mt][0], al2, &wh[0]);
                mma_bf16(oacc[mt][1], al2, &wh[2]);
                mma_bf16(oacc[mt][0], ah2, &wl[0]);
                mma_bf16(oacc[mt][1], ah2, &wl[2]);
            }
        }

        // ---- stage partials into dedicated buffers by nw ----
        {
            float* obuf = smf + SB_OUT / 4 + nw * 2560;
#pragma unroll
            for (int mt = 0; mt < 2; ++mt) {
                int p0 = mw * 32 + mt * 16 + (lane >> 2);
                float* s0 = obuf + p0 * 20;
                float* s1 = obuf + (p0 + 8) * 20;
                *(float2*)(s0 + 2 * q)     = make_float2(oacc[mt][0][0], oacc[mt][0][1]);
                *(float2*)(s0 + 8 + 2 * q) = make_float2(oacc[mt][1][0], oacc[mt][1][1]);
                *(float2*)(s1 + 2 * q)     = make_float2(oacc[mt][0][2], oacc[mt][0][3]);
                *(float2*)(s1 + 8 + 2 * q) = make_float2(oacc[mt][1][2], oacc[mt][1][3]);
            }
        }
        __syncthreads();

        // ---- sum 4 partials + coalesced store (512 float4, 1 pass) ----
        {
            const long obase = ((long)b << 18) + ((long)h << 4);
            const float* o0 = smf + SB_OUT / 4;
            int p = tid >> 2, c4 = (tid & 3) * 4;
            float4 v0 = *(const float4*)(o0 + p * 20 + c4);
            float4 v1 = *(const float4*)(o0 + 2560 + p * 20 + c4);
            float4 v2 = *(const float4*)(o0 + 5120 + p * 20 + c4);
            float4 v3 = *(const float4*)(o0 + 7680 + p * 20 + c4);
            float4 v = make_float4(v0.x + v1.x + v2.x + v3.x,
                                   v0.y + v1.y + v2.y + v3.y,
                                   v0.z + v1.z + v2.z + v3.z,
                                   v0.w + v1.w + v2.w + v3.w);
            *(float4*)(out + obase + ((long)p << 11) + c4) = v;
        }
        // next iteration's top __syncthreads orders store reads vs new writes
    }
}

extern "C" void kernel_launch(void* const* d_in, const int* in_sizes, int n_in,
                              void* d_out, int out_size) {
    const float* x  = (const float*)d_in[0];
    const float* Wx = (const float*)d_in[1];
    const float* bx = (const float*)d_in[2];
    const float* Wy = (const float*)d_in[3];
    const float* by = (const float*)d_in[4];
    const float* W1 = (const float*)d_in[5];
    const float* b1 = (const float*)d_in[6];
    const float* W2 = (const float*)d_in[7];
    const float* b2 = (const float*)d_in[8];
    float* out = (float*)d_out;

    prep_w_kernel<<<72, 256>>>(Wx, Wy, W1, b1, bx, by, W2);
    prep_t_kernel<<<4096, 256>>>(x);

    cudaFuncSetAttribute(nca_mma_kernel,
                         cudaFuncAttributeMaxDynamicSharedMemorySize, SMEM_BYTES);
    nca_mma_kernel<<<NBLOCKS, NTHREADS, SMEM_BYTES>>>(b2, out);
}

// round 11
// speedup vs baseline: 1.6205x; 1.3113x over previous
#include <cuda_runtime.h>
#include <cuda_bf16.h>
#include <cstdint>

// ============================================================================
// out = W2 @ relu( h ) + b2,  h = [convy(x)|x] x W~  +  u*s(x)  + b1f
// where s = sobel^T * (sum_i x_i)  (rank-1 conv_x path, Wx is tiled sobel).
// Phase1: feat = patch(144) x [Wy | K_s]  (M128 x N24 x K144), 8 warps.
// Phase2: h = [feat(16) | x(16)] x W~ (K=32) + u*s, 16 warps 8(M)x2(N).
// All GEMMs bf16 2-term split, 3 cross products. cp.async prefetch of x rows.
// ============================================================================

#define NTHREADS 512
#define TILES_PER_BLOCK 4
#define NBLOCKS 1024

// ---- SMEM byte offsets ----
#define SB_B1H   0          // [32 rows][304B] bf16 (Wy | K_s | zeros)
#define SB_B1L   9728
#define SB_BTH   19456      // [128][80B] bf16 W~
#define SB_BTL   29696
#define SB_W2H   39936      // [16][304B]
#define SB_W2L   44800
#define SB_AT0H  49664      // x rows buf0 hi: 130 x 112B
#define SB_AT0L  64224
#define SB_AT1H  78784
#define SB_AT1L  93344
#define SB_FH    107904     // feat hi [128][48B]
#define SB_FL    114048
#define SB_S     120192     // s[128] f32
#define SB_B1F   120704     // 128 f32
#define SB_U     121216     // 128 f32
#define SB_B2    121728     // 16 f32
#define SB_OUT   121792     // 2 x [128][20] f32 partials
#define SMEM_BYTES 142272
#define AT_LO_OFF 14560

__device__ __nv_bfloat16 g_B1h[32 * 152];
__device__ __nv_bfloat16 g_B1l[32 * 152];
__device__ __nv_bfloat16 g_Bth[128 * 40];
__device__ __nv_bfloat16 g_Btl[128 * 40];
__device__ __nv_bfloat16 g_W2h[16 * 152];
__device__ __nv_bfloat16 g_W2l[16 * 152];
__device__ float g_B1f[128];
__device__ float g_u[128];
__device__ __nv_bfloat16 g_xTh[32 * 128 * 128 * 16];
__device__ __nv_bfloat16 g_xTl[32 * 128 * 128 * 16];

// ---------------------------------------------------------------------------
__device__ __forceinline__ uint32_t smem_u32(const void* p) {
    uint32_t a;
    asm("{ .reg .u64 t; cvta.to.shared.u64 t, %1; cvt.u32.u64 %0, t; }" : "=r"(a) : "l"(p));
    return a;
}
__device__ __forceinline__ void ldsm_x4(uint32_t* r, uint32_t addr) {
    asm volatile("ldmatrix.sync.aligned.m8n8.x4.shared.b16 {%0,%1,%2,%3}, [%4];"
                 : "=r"(r[0]), "=r"(r[1]), "=r"(r[2]), "=r"(r[3]) : "r"(addr));
}
__device__ __forceinline__ void mma_bf16(float* c, const uint32_t* a, const uint32_t* b) {
    asm volatile("mma.sync.aligned.m16n8k16.row.col.f32.bf16.bf16.f32 "
                 "{%0,%1,%2,%3}, {%4,%5,%6,%7}, {%8,%9}, {%0,%1,%2,%3};"
                 : "+f"(c[0]), "+f"(c[1]), "+f"(c[2]), "+f"(c[3])
                 : "r"(a[0]), "r"(a[1]), "r"(a[2]), "r"(a[3]), "r"(b[0]), "r"(b[1]));
}
__device__ __forceinline__ uint32_t cvt_bf16x2(float hi, float lo) {
    uint32_t r;
    asm("cvt.rn.bf16x2.f32 %0, %1, %2;" : "=r"(r) : "f"(hi), "f"(lo));
    return r;
}
#define CP_COMMIT() asm volatile("cp.async.commit_group;" ::: "memory")
#define CP_WAIT1()  asm volatile("cp.async.wait_group 1;" ::: "memory")

__device__ __forceinline__ void prefetch_at(int tile, uint32_t at_hi, int tid) {
    const int b = tile >> 7, h = tile & 127;
#pragma unroll
    for (int it = 0; it < 2; ++it) {
        int idx = tid + it * NTHREADS;
        if (idx >= 780) break;
        int prec = idx / 390;
        int rem = idx - prec * 390;
        int kh = rem / 130;
        int pp = rem - kh * 130;
        int hh = h + kh - 1, w = pp - 1;
        bool ok = ((unsigned)hh < 128u) && ((unsigned)w < 128u);
        const __nv_bfloat16* base = prec ? g_xTl : g_xTh;
        const __nv_bfloat16* src = base +
            ((((long)(b << 7) + (ok ? hh : 0)) << 7) + (ok ? w : 0)) * 16;
        uint32_t dst = at_hi + (uint32_t)prec * AT_LO_OFF +
                       (uint32_t)pp * 112 + (uint32_t)kh * 32;
        int sz = ok ? 16 : 0;
        asm volatile("cp.async.ca.shared.global [%0], [%1], 16, %2;"
                     :: "r"(dst), "l"(src), "r"(sz) : "memory");
        asm volatile("cp.async.ca.shared.global [%0], [%1], 16, %2;"
                     :: "r"(dst + 16), "l"(src + 8), "r"(sz) : "memory");
    }
}

// ---------------------------------------------------------------------------
__global__ void prep_w_kernel(const float* __restrict__ Wx,
                              const float* __restrict__ Wy,
                              const float* __restrict__ W1,
                              const float* __restrict__ b1,
                              const float* __restrict__ bx,
                              const float* __restrict__ by,
                              const float* __restrict__ W2) {
    int idx = blockIdx.x * blockDim.x + threadIdx.x;
    // B1 = [Wy rows 0..15 | K_s row 16 | zeros], k-order (kh,kw,i), pad 152
    if (idx < 32 * 152) {
        int o = idx / 152, k = idx - o * 152;
        float f = 0.f;
        if (k < 144) {
            int kh = k / 48, kw = (k % 48) / 16, i = k & 15;
            int kk = kh * 3 + kw;
            if (o < 16)       f = Wy[(o * 16 + i) * 9 + kk];
            else if (o == 16) f = Wx[kk];   // tiled sobel: same for all (o,i)
        }
        __nv_bfloat16 hi = __float2bfloat16(f);
        __nv_bfloat16 lo = __float2bfloat16(f - __bfloat162float(hi));
        g_B1h[idx] = hi;
        g_B1l[idx] = lo;
    }
    // W~ rows m, cols c: c<16 -> W1[m][16+c] (convy), 16<=c<32 -> W1[m][32+c-16]
    if (idx < 128 * 40) {
        int m = idx / 40, c = idx - m * 40;
        float f = (c < 32) ? W1[m * 48 + 16 + c] : 0.f;
        __nv_bfloat16 hi = __float2bfloat16(f);
        __nv_bfloat16 lo = __float2bfloat16(f - __bfloat162float(hi));
        g_Bth[idx] = hi;
        g_Btl[idx] = lo;
    }
    if (idx < 2048) {
        int o = idx >> 7, m = idx & 127;
        float f = W2[o * 128 + m];
        __nv_bfloat16 hi = __float2bfloat16(f);
        __nv_bfloat16 lo = __float2bfloat16(f - __bfloat162float(hi));
        g_W2h[o * 152 + m] = hi;
        g_W2l[o * 152 + m] = lo;
    }
    if (idx < 128) {
        float s = b1[idx];
        float uu = 0.f;
        const float* w1r = W1 + idx * 48;
#pragma unroll
        for (int o = 0; o < 16; ++o) {
            s += w1r[o] * bx[o] + w1r[16 + o] * by[o];
            uu += w1r[o];
        }
        g_B1f[idx] = s;
        g_u[idx] = uu;
    }
}

__global__ void prep_t_kernel(const float* __restrict__ x) {
    __shared__ float s[16 * 132];
    const int bid = blockIdx.x;
    const int b = bid >> 7, h = bid & 127;
    const int tid = threadIdx.x;
#pragma unroll
    for (int t = tid; t < 2048; t += 256) {
        int c = t >> 7, w = t & 127;
        s[c * 132 + w] = x[((b * 16 + c) << 14) + (h << 7) + w];
    }
    __syncthreads();
#pragma unroll
    for (int t = tid; t < 2048; t += 256) {
        int w = t >> 4, c = t & 15;
        float v = s[c * 132 + w];
        __nv_bfloat16 hi = __float2bfloat16(v);
        __nv_bfloat16 lo = __float2bfloat16(v - __bfloat162float(hi));
        long off = ((((long)(b << 7) + h) << 7) + w) * 16 + c;
        g_xTh[off] = hi;
        g_xTl[off] = lo;
    }
}

// ---------------------------------------------------------------------------
__global__ __launch_bounds__(NTHREADS, 1)
void nca_mma_kernel(const float* __restrict__ b2g,
                    float* __restrict__ out) {
    extern __shared__ char sm[];
    float* smf = (float*)sm;
    const uint32_t smem_base = smem_u32(sm);
    const int tid = threadIdx.x;
    const int wid = tid >> 5;
    const int lane = tid & 31;
    const int q = lane & 3;
    const int r = lane >> 2;
    const int mw2 = wid & 7;       // phase2 M-warp (pixels mw2*16..+16)
    const int nw2 = wid >> 3;      // phase2 N-warp (hidden nw2*64..+64)
    const int tile_base = blockIdx.x * TILES_PER_BLOCK;

    // ---- stage persistent weights ----
    {
        uint4* d;
        const uint4* s4;
        d = (uint4*)(sm + SB_B1H); s4 = (const uint4*)g_B1h;
        for (int i = tid; i < 608; i += NTHREADS) d[i] = s4[i];
        d = (uint4*)(sm + SB_B1L); s4 = (const uint4*)g_B1l;
        for (int i = tid; i < 608; i += NTHREADS) d[i] = s4[i];
        d = (uint4*)(sm + SB_BTH); s4 = (const uint4*)g_Bth;
        for (int i = tid; i < 640; i += NTHREADS) d[i] = s4[i];
        d = (uint4*)(sm + SB_BTL); s4 = (const uint4*)g_Btl;
        for (int i = tid; i < 640; i += NTHREADS) d[i] = s4[i];
        d = (uint4*)(sm + SB_W2H); s4 = (const uint4*)g_W2h;
        for (int i = tid; i < 304; i += NTHREADS) d[i] = s4[i];
        d = (uint4*)(sm + SB_W2L); s4 = (const uint4*)g_W2l;
        for (int i = tid; i < 304; i += NTHREADS) d[i] = s4[i];
        if (tid < 128) smf[SB_B1F / 4 + tid] = g_B1f[tid];
        if (tid < 128) smf[SB_U / 4 + tid] = g_u[tid];
        if (tid < 16)  smf[SB_B2 / 4 + tid] = b2g[tid];
    }
    prefetch_at(tile_base, smem_base + SB_AT0H, tid);
    CP_COMMIT();
    __syncthreads();

    // ldsm lane decomposition
    const uint32_t lrow = (uint32_t)((lane & 7) + ((lane >> 3) & 1) * 8);
    const uint32_t lcol16 = (uint32_t)((lane >> 4) * 16);
    const uint32_t brow = (uint32_t)((lane & 7) + (lane >> 4) * 8);
    const uint32_t bcol16 = (uint32_t)(((lane >> 3) & 1) * 16);

    const uint32_t b1_addr = smem_base + SB_B1H + brow * 304 + bcol16;
    const uint32_t bt_addr = smem_base + SB_BTH +
        ((uint32_t)(nw2 * 64) + brow) * 80 + bcol16;
    const uint32_t f_addr = smem_base + SB_FH +
        ((uint32_t)(mw2 * 16) + lrow) * 48 + lcol16;
    const uint32_t w2_addr = smem_base + SB_W2H + brow * 304 + bcol16 +
        (uint32_t)(nw2 * 128);

#pragma unroll
    for (int j = 0; j < TILES_PER_BLOCK; ++j) {
        const int tile = tile_base + j;
        const int b = tile >> 7;
        const int h = tile & 127;
        const uint32_t at_cur = smem_base + ((j & 1) ? SB_AT1H : SB_AT0H);
        const uint32_t at_nxt = smem_base + ((j & 1) ? SB_AT0H : SB_AT1H);

        {
            int tn = tile + 1;
            if (tn > NBLOCKS * TILES_PER_BLOCK - 1) tn = NBLOCKS * TILES_PER_BLOCK - 1;
            prefetch_at(tn, at_nxt, tid);
            CP_COMMIT();
        }
        CP_WAIT1();
        __syncthreads();

        // ================= PHASE 1 (warps 0..7): feat = patch x [Wy|K_s] ====
        if (wid < 8) {
            float ay[3][4];
#pragma unroll
            for (int g = 0; g < 3; ++g)
#pragma unroll
                for (int e = 0; e < 4; ++e) ay[g][e] = 0.f;

            const uint32_t a_base = at_cur +
                ((uint32_t)(wid * 16) + lrow) * 112 + lcol16;
#pragma unroll
            for (int ks = 0; ks < 9; ++ks) {
                const int kh = ks / 3, kw = ks - 3 * kh;
                uint32_t aa = a_base + (uint32_t)(kw * 112 + kh * 32);
                uint32_t ah[4], al[4];
                ldsm_x4(ah, aa);
                ldsm_x4(al, aa + AT_LO_OFF);
                const uint32_t kb = (uint32_t)(ks * 32);
                uint32_t bh[4], bl[4], bh2[4], bl2[4];
                ldsm_x4(bh, b1_addr + kb);
                ldsm_x4(bl, b1_addr + kb + (SB_B1L - SB_B1H));
                ldsm_x4(bh2, b1_addr + 16 * 304 + kb);
                ldsm_x4(bl2, b1_addr + 16 * 304 + kb + (SB_B1L - SB_B1H));
                mma_bf16(ay[0], ah, &bh[0]);
                mma_bf16(ay[1], ah, &bh[2]);
                mma_bf16(ay[2], ah, &bh2[0]);
                mma_bf16(ay[0], al, &bh[0]);
                mma_bf16(ay[1], al, &bh[2]);
                mma_bf16(ay[2], al, &bh2[0]);
                mma_bf16(ay[0], ah, &bl[0]);
                mma_bf16(ay[1], ah, &bl[2]);
                mma_bf16(ay[2], ah, &bl2[0]);
            }

            // repack feat (groups 0,1) -> bf16 hi/lo A-matrix in SMEM
            {
                const uint32_t p0 = (uint32_t)(wid * 16 + r);
#pragma unroll
                for (int g = 0; g < 2; ++g) {
                    float y0 = ay[g][0], y1 = ay[g][1], y2 = ay[g][2], y3 = ay[g][3];
                    uint32_t h0 = cvt_bf16x2(y1, y0);
                    uint32_t h1 = cvt_bf16x2(y3, y2);
                    uint32_t l0 = cvt_bf16x2(y1 - __uint_as_float(h0 & 0xFFFF0000u),
                                             y0 - __uint_as_float(h0 << 16));
                    uint32_t l1 = cvt_bf16x2(y3 - __uint_as_float(h1 & 0xFFFF0000u),
                                             y2 - __uint_as_float(h1 << 16));
                    uint32_t off0 = p0 * 48 + (uint32_t)(g * 16 + q * 4);
                    uint32_t off1 = (p0 + 8) * 48 + (uint32_t)(g * 16 + q * 4);
                    *(uint32_t*)(sm + SB_FH + off0) = h0;
                    *(uint32_t*)(sm + SB_FH + off1) = h1;
                    *(uint32_t*)(sm + SB_FL + off0) = l0;
                    *(uint32_t*)(sm + SB_FL + off1) = l1;
                }
                if (q == 0) {
                    smf[SB_S / 4 + p0] = ay[2][0];
                    smf[SB_S / 4 + p0 + 8] = ay[2][2];
                }
            }
        }
        __syncthreads();

        // ================= PHASE 2 (all warps): h = [feat|x] x W~ + u*s =====
        float acc[8][4];
#pragma unroll
        for (int g = 0; g < 8; ++g) {
            float2 bv = *(const float2*)(smf + SB_B1F / 4 + nw2 * 64 + g * 8 + q * 2);
            acc[g][0] = bv.x; acc[g][1] = bv.y;
            acc[g][2] = bv.x; acc[g][3] = bv.y;
        }

#pragma unroll
        for (int kst = 0; kst < 2; ++kst) {
            uint32_t ah[4], al[4];
            if (kst == 0) {
                ldsm_x4(ah, f_addr);
                ldsm_x4(al, f_addr + (SB_FL - SB_FH));
            } else {
                uint32_t xa = at_cur + ((uint32_t)(mw2 * 16 + 1) + lrow) * 112 + 32 + lcol16;
                ldsm_x4(ah, xa);
                ldsm_x4(al, xa + AT_LO_OFF);
            }
            const uint32_t kb = (uint32_t)(kst * 32);
#pragma unroll
            for (int cc = 0; cc < 4; ++cc) {
                uint32_t bh[4], bl[4];
                uint32_t ba = bt_addr + (uint32_t)(cc * 16) * 80 + kb;
                ldsm_x4(bh, ba);
                ldsm_x4(bl, ba + (SB_BTL - SB_BTH));
                mma_bf16(acc[2 * cc],     ah, &bh[0]);
                mma_bf16(acc[2 * cc + 1], ah, &bh[2]);
                mma_bf16(acc[2 * cc],     al, &bh[0]);
                mma_bf16(acc[2 * cc + 1], al, &bh[2]);
                mma_bf16(acc[2 * cc],     ah, &bl[0]);
                mma_bf16(acc[2 * cc + 1], ah, &bl[2]);
            }
        }

        // rank-1 conv_x path: acc += u[m] * s[p]
        {
            float s0 = smf[SB_S / 4 + mw2 * 16 + r];
            float s1 = smf[SB_S / 4 + mw2 * 16 + r + 8];
#pragma unroll
            for (int g = 0; g < 8; ++g) {
                float2 u2 = *(const float2*)(smf + SB_U / 4 + nw2 * 64 + g * 8 + q * 2);
                acc[g][0] += u2.x * s0;
                acc[g][1] += u2.y * s0;
                acc[g][2] += u2.x * s1;
                acc[g][3] += u2.y * s1;
            }
        }

        // ================= TAIL: out16 += relu(h) x W2^T (K split by nw2) ===
        float oacc[2][4];
#pragma unroll
        for (int jj = 0; jj < 2; ++jj) {
            float2 bv = *(const float2*)(smf + SB_B2 / 4 + jj * 8 + q * 2);
            float b0 = (nw2 == 0) ? bv.x : 0.f;
            float b1v = (nw2 == 0) ? bv.y : 0.f;
            oacc[jj][0] = b0; oacc[jj][1] = b1v;
            oacc[jj][2] = b0; oacc[jj][3] = b1v;
        }

#pragma unroll
        for (int kt = 0; kt < 4; ++kt) {
            uint32_t wh[4], wl[4];
            uint32_t wa = w2_addr + (uint32_t)(kt * 32);
            ldsm_x4(wh, wa);
            ldsm_x4(wl, wa + (SB_W2L - SB_W2H));
            float y0 = fmaxf(acc[2 * kt][0], 0.f),     y1 = fmaxf(acc[2 * kt][1], 0.f);
            float y2 = fmaxf(acc[2 * kt][2], 0.f),     y3 = fmaxf(acc[2 * kt][3], 0.f);
            float z0 = fmaxf(acc[2 * kt + 1][0], 0.f), z1 = fmaxf(acc[2 * kt + 1][1], 0.f);
            float z2 = fmaxf(acc[2 * kt + 1][2], 0.f), z3 = fmaxf(acc[2 * kt + 1][3], 0.f);
            uint32_t ah2[4], al2[4];
            ah2[0] = cvt_bf16x2(y1, y0);
            ah2[1] = cvt_bf16x2(y3, y2);
            ah2[2] = cvt_bf16x2(z1, z0);
            ah2[3] = cvt_bf16x2(z3, z2);
            al2[0] = cvt_bf16x2(y1 - __uint_as_float(ah2[0] & 0xFFFF0000u),
                                y0 - __uint_as_float(ah2[0] << 16));
            al2[1] = cvt_bf16x2(y3 - __uint_as_float(ah2[1] & 0xFFFF0000u),
                                y2 - __uint_as_float(ah2[1] << 16));
            al2[2] = cvt_bf16x2(z1 - __uint_as_float(ah2[2] & 0xFFFF0000u),
                                z0 - __uint_as_float(ah2[2] << 16));
            al2[3] = cvt_bf16x2(z3 - __uint_as_float(ah2[3] & 0xFFFF0000u),
                                z2 - __uint_as_float(ah2[3] << 16));
            mma_bf16(oacc[0], ah2, &wh[0]);
            mma_bf16(oacc[1], ah2, &wh[2]);
            mma_bf16(oacc[0], al2, &wh[0]);
            mma_bf16(oacc[1], al2, &wh[2]);
            mma_bf16(oacc[0], ah2, &wl[0]);
            mma_bf16(oacc[1], ah2, &wl[2]);
        }

        // ---- stage 2 partial buffers by nw2 ----
        {
            float* obuf = smf + SB_OUT / 4 + nw2 * 2560;
            int p0 = mw2 * 16 + r;
            float* s0 = obuf + p0 * 20;
            float* s1 = obuf + (p0 + 8) * 20;
            *(float2*)(s0 + 2 * q)     = make_float2(oacc[0][0], oacc[0][1]);
            *(float2*)(s0 + 8 + 2 * q) = make_float2(oacc[1][0], oacc[1][1]);
            *(float2*)(s1 + 2 * q)     = make_float2(oacc[0][2], oacc[0][3]);
            *(float2*)(s1 + 8 + 2 * q) = make_float2(oacc[1][2], oacc[1][3]);
        }
        __syncthreads();

        // ---- sum partials + coalesced store ----
        {
            const long obase = ((long)b << 18) + ((long)h << 4);
            const float* o0 = smf + SB_OUT / 4;
            int p = tid >> 2, c4 = (tid & 3) * 4;
            float4 v0 = *(const float4*)(o0 + p * 20 + c4);
            float4 v1 = *(const float4*)(o0 + 2560 + p * 20 + c4);
            float4 v = make_float4(v0.x + v1.x, v0.y + v1.y,
                                   v0.z + v1.z, v0.w + v1.w);
            *(float4*)(out + obase + ((long)p << 11) + c4) = v;
        }
        // next iteration's top sync orders partial-buffer & feat reuse
    }
}

extern "C" void kernel_launch(void* const* d_in, const int* in_sizes, int n_in,
                              void* d_out, int out_size) {
    const float* x  = (const float*)d_in[0];
    const float* Wx = (const float*)d_in[1];
    const float* bx = (const float*)d_in[2];
    const float* Wy = (const float*)d_in[3];
    const float* by = (const float*)d_in[4];
    const float* W1 = (const float*)d_in[5];
    const float* b1 = (const float*)d_in[6];
    const float* W2 = (const float*)d_in[7];
    const float* b2 = (const float*)d_in[8];
    float* out = (float*)d_out;

    prep_w_kernel<<<72, 256>>>(Wx, Wy, W1, b1, bx, by, W2);
    prep_t_kernel<<<4096, 256>>>(x);

    cudaFuncSetAttribute(nca_mma_kernel,
                         cudaFuncAttributeMaxDynamicSharedMemorySize, SMEM_BYTES);
    nca_mma_kernel<<<NBLOCKS, NTHREADS, SMEM_BYTES>>>(b2, out);
}

// round 12
// speedup vs baseline: 1.7566x; 1.0840x over previous
#include <cuda_runtime.h>
#include <cuda_bf16.h>
#include <cstdint>

// ============================================================================
// out = W2 @ relu( h ) + b2,  h = [convy(x)|x] x W~  +  u*s(x)  + b1f
// Row-pair tiles: 256 pixels (2 h-rows) per iteration; x stored as 4 h-slabs
// of channel-last bf16 (hi/lo) rows. Phase1: feat = patch x [Wy|K_s]
// (M256 x N24 x K144, 8 warps x M32). Phase2: h = [feat|x] x W~ (K32) + u*s,
// 16 warps 8(M)x2(N), 2 m-tiles share B fragments. Tensor-core tail.
// ============================================================================

#define NTHREADS 512
#define PAIRS_PER_BLOCK 2
#define NBLOCKS 1024                 // 2048 pairs total

// ---- SMEM byte offsets ----
#define SB_B1H   0                   // [32][304] bf16 (Wy | K_s | zeros)
#define SB_B1L   9728
#define SB_BTH   19456               // [128][80] bf16 W~
#define SB_BTL   29696
#define SB_W2H   39936               // [16][304]
#define SB_W2L   44800
#define SB_AT0   49664               // buf0: [prec2][slab4][130][32B]
#define SB_AT1   82944               // buf1
#define SB_FH    116224              // feat hi [256][48B]
#define SB_FL    128512
#define SB_S     140800              // s[256] f32
#define SB_B1F   141824              // 128 f32
#define SB_U     142336              // 128 f32
#define SB_B2    142848              // 16 f32
#define SB_OUT   142912              // 2 x [256][20] f32 partials
#define SMEM_BYTES 183872
#define AT_LO_OFF 16640              // prec stride
#define SLAB 4160                    // slab stride (130*32)

__device__ __nv_bfloat16 g_B1h[32 * 152];
__device__ __nv_bfloat16 g_B1l[32 * 152];
__device__ __nv_bfloat16 g_Bth[128 * 40];
__device__ __nv_bfloat16 g_Btl[128 * 40];
__device__ __nv_bfloat16 g_W2h[16 * 152];
__device__ __nv_bfloat16 g_W2l[16 * 152];
__device__ float g_B1f[128];
__device__ float g_u[128];
__device__ __nv_bfloat16 g_xTh[32 * 128 * 128 * 16];
__device__ __nv_bfloat16 g_xTl[32 * 128 * 128 * 16];

// ---------------------------------------------------------------------------
__device__ __forceinline__ uint32_t smem_u32(const void* p) {
    uint32_t a;
    asm("{ .reg .u64 t; cvta.to.shared.u64 t, %1; cvt.u32.u64 %0, t; }" : "=r"(a) : "l"(p));
    return a;
}
__device__ __forceinline__ void ldsm_x4(uint32_t* r, uint32_t addr) {
    asm volatile("ldmatrix.sync.aligned.m8n8.x4.shared.b16 {%0,%1,%2,%3}, [%4];"
                 : "=r"(r[0]), "=r"(r[1]), "=r"(r[2]), "=r"(r[3]) : "r"(addr));
}
__device__ __forceinline__ void mma_bf16(float* c, const uint32_t* a, const uint32_t* b) {
    asm volatile("mma.sync.aligned.m16n8k16.row.col.f32.bf16.bf16.f32 "
                 "{%0,%1,%2,%3}, {%4,%5,%6,%7}, {%8,%9}, {%0,%1,%2,%3};"
                 : "+f"(c[0]), "+f"(c[1]), "+f"(c[2]), "+f"(c[3])
                 : "r"(a[0]), "r"(a[1]), "r"(a[2]), "r"(a[3]), "r"(b[0]), "r"(b[1]));
}
__device__ __forceinline__ uint32_t cvt_bf16x2(float hi, float lo) {
    uint32_t r;
    asm("cvt.rn.bf16x2.f32 %0, %1, %2;" : "=r"(r) : "f"(hi), "f"(lo));
    return r;
}
#define CP_COMMIT() asm volatile("cp.async.commit_group;" ::: "memory")
#define CP_WAIT1()  asm volatile("cp.async.wait_group 1;" ::: "memory")

// prefetch x slabs h0-1..h0+2 (hi+lo) for pair into at buffer
__device__ __forceinline__ void prefetch_at(int pair, uint32_t at_buf, int tid) {
    const int b = pair >> 6, h0 = (pair & 63) << 1;
    for (int it = 0; it < 5; ++it) {
        int idx = tid + it * NTHREADS;
        if (idx >= 2080) break;
        int chunk = idx & 1;
        int t = idx >> 1;
        int pp = t % 130;
        int t2 = t / 130;
        int slab = t2 & 3, prec = t2 >> 2;
        int hh = h0 - 1 + slab, w = pp - 1;
        bool ok = ((unsigned)hh < 128u) && ((unsigned)w < 128u);
        const __nv_bfloat16* base = prec ? g_xTl : g_xTh;
        const __nv_bfloat16* src = base +
            ((((long)(b << 7) + (ok ? hh : 0)) << 7) + (ok ? w : 0)) * 16 + chunk * 8;
        uint32_t dst = at_buf + (uint32_t)prec * AT_LO_OFF +
                       (uint32_t)slab * SLAB + (uint32_t)pp * 32 + (uint32_t)chunk * 16;
        int sz = ok ? 16 : 0;
        asm volatile("cp.async.ca.shared.global [%0], [%1], 16, %2;"
                     :: "r"(dst), "l"(src), "r"(sz) : "memory");
    }
}

// ---------------------------------------------------------------------------
__global__ void prep_w_kernel(const float* __restrict__ Wx,
                              const float* __restrict__ Wy,
                              const float* __restrict__ W1,
                              const float* __restrict__ b1,
                              const float* __restrict__ bx,
                              const float* __restrict__ by,
                              const float* __restrict__ W2) {
    int idx = blockIdx.x * blockDim.x + threadIdx.x;
    if (idx < 32 * 152) {
        int o = idx / 152, k = idx - o * 152;
        float f = 0.f;
        if (k < 144) {
            int kh = k / 48, kw = (k % 48) / 16, i = k & 15;
            int kk = kh * 3 + kw;
            if (o < 16)       f = Wy[(o * 16 + i) * 9 + kk];
            else if (o == 16) f = Wx[kk];
        }
        __nv_bfloat16 hi = __float2bfloat16(f);
        __nv_bfloat16 lo = __float2bfloat16(f - __bfloat162float(hi));
        g_B1h[idx] = hi;
        g_B1l[idx] = lo;
    }
    if (idx < 128 * 40) {
        int m = idx / 40, c = idx - m * 40;
        float f = (c < 32) ? W1[m * 48 + 16 + c] : 0.f;
        __nv_bfloat16 hi = __float2bfloat16(f);
        __nv_bfloat16 lo = __float2bfloat16(f - __bfloat162float(hi));
        g_Bth[idx] = hi;
        g_Btl[idx] = lo;
    }
    if (idx < 2048) {
        int o = idx >> 7, m = idx & 127;
        float f = W2[o * 128 + m];
        __nv_bfloat16 hi = __float2bfloat16(f);
        __nv_bfloat16 lo = __float2bfloat16(f - __bfloat162float(hi));
        g_W2h[o * 152 + m] = hi;
        g_W2l[o * 152 + m] = lo;
    }
    if (idx < 128) {
        float s = b1[idx];
        float uu = 0.f;
        const float* w1r = W1 + idx * 48;
#pragma unroll
        for (int o = 0; o < 16; ++o) {
            s += w1r[o] * bx[o] + w1r[16 + o] * by[o];
            uu += w1r[o];
        }
        g_B1f[idx] = s;
        g_u[idx] = uu;
    }
}

__global__ void prep_t_kernel(const float* __restrict__ x) {
    __shared__ float s[16 * 132];
    const int bid = blockIdx.x;
    const int b = bid >> 7, h = bid & 127;
    const int tid = threadIdx.x;
#pragma unroll
    for (int t = tid; t < 2048; t += 256) {
        int c = t >> 7, w = t & 127;
        s[c * 132 + w] = x[((b * 16 + c) << 14) + (h << 7) + w];
    }
    __syncthreads();
#pragma unroll
    for (int t = tid; t < 2048; t += 256) {
        int w = t >> 4, c = t & 15;
        float v = s[c * 132 + w];
        __nv_bfloat16 hi = __float2bfloat16(v);
        __nv_bfloat16 lo = __float2bfloat16(v - __bfloat162float(hi));
        long off = ((((long)(b << 7) + h) << 7) + w) * 16 + c;
        g_xTh[off] = hi;
        g_xTl[off] = lo;
    }
}

// ---------------------------------------------------------------------------
__global__ __launch_bounds__(NTHREADS, 1)
void nca_mma_kernel(const float* __restrict__ b2g,
                    float* __restrict__ out) {
    extern __shared__ char sm[];
    float* smf = (float*)sm;
    const uint32_t smem_base = smem_u32(sm);
    const int tid = threadIdx.x;
    const int wid = tid >> 5;
    const int lane = tid & 31;
    const int q = lane & 3;
    const int r = lane >> 2;
    const int mw2 = wid & 7;
    const int nw2 = wid >> 3;
    const int pair_base = blockIdx.x * PAIRS_PER_BLOCK;

    // ---- stage persistent weights ----
    {
        uint4* d;
        const uint4* s4;
        d = (uint4*)(sm + SB_B1H); s4 = (const uint4*)g_B1h;
        for (int i = tid; i < 608; i += NTHREADS) d[i] = s4[i];
        d = (uint4*)(sm + SB_B1L); s4 = (const uint4*)g_B1l;
        for (int i = tid; i < 608; i += NTHREADS) d[i] = s4[i];
        d = (uint4*)(sm + SB_BTH); s4 = (const uint4*)g_Bth;
        for (int i = tid; i < 640; i += NTHREADS) d[i] = s4[i];
        d = (uint4*)(sm + SB_BTL); s4 = (const uint4*)g_Btl;
        for (int i = tid; i < 640; i += NTHREADS) d[i] = s4[i];
        d = (uint4*)(sm + SB_W2H); s4 = (const uint4*)g_W2h;
        for (int i = tid; i < 304; i += NTHREADS) d[i] = s4[i];
        d = (uint4*)(sm + SB_W2L); s4 = (const uint4*)g_W2l;
        for (int i = tid; i < 304; i += NTHREADS) d[i] = s4[i];
        if (tid < 128) smf[SB_B1F / 4 + tid] = g_B1f[tid];
        if (tid < 128) smf[SB_U / 4 + tid] = g_u[tid];
        if (tid < 16)  smf[SB_B2 / 4 + tid] = b2g[tid];
    }
    prefetch_at(pair_base, smem_base + SB_AT0, tid);
    CP_COMMIT();
    __syncthreads();

    const uint32_t lrow = (uint32_t)((lane & 7) + ((lane >> 3) & 1) * 8);
    const uint32_t lcol16 = (uint32_t)((lane >> 4) * 16);
    const uint32_t brow = (uint32_t)((lane & 7) + (lane >> 4) * 8);
    const uint32_t bcol16 = (uint32_t)(((lane >> 3) & 1) * 16);

    const uint32_t b1_addr = smem_base + SB_B1H + brow * 304 + bcol16;
    const uint32_t bt_addr = smem_base + SB_BTH +
        ((uint32_t)(nw2 * 64) + brow) * 80 + bcol16;
    const uint32_t w2_addr = smem_base + SB_W2H + brow * 304 + bcol16 +
        (uint32_t)(nw2 * 128);

#pragma unroll
    for (int j = 0; j < PAIRS_PER_BLOCK; ++j) {
        const int pair = pair_base + j;
        const int b = pair >> 6;
        const int h0 = (pair & 63) << 1;
        const uint32_t at_cur = smem_base + ((j & 1) ? SB_AT1 : SB_AT0);
        const uint32_t at_nxt = smem_base + ((j & 1) ? SB_AT0 : SB_AT1);

        {
            int tn = pair + 1;
            if (tn > NBLOCKS * PAIRS_PER_BLOCK - 1) tn = NBLOCKS * PAIRS_PER_BLOCK - 1;
            prefetch_at(tn, at_nxt, tid);
            CP_COMMIT();
        }
        CP_WAIT1();
        __syncthreads();

        // ============ PHASE 1 (warps 0..7): feat = patch x [Wy|K_s] ========
        if (wid < 8) {
            float ay[2][3][4];
#pragma unroll
            for (int mt = 0; mt < 2; ++mt)
#pragma unroll
                for (int g = 0; g < 3; ++g)
#pragma unroll
                    for (int e = 0; e < 4; ++e) ay[mt][g][e] = 0.f;

            const uint32_t w_base = (uint32_t)(wid * 16);
#pragma unroll
            for (int ks = 0; ks < 9; ++ks) {
                const int kh = ks / 3, kw = ks - 3 * kh;
                uint32_t ah[2][4], al[2][4];
#pragma unroll
                for (int mt = 0; mt < 2; ++mt) {
                    uint32_t aa = at_cur + (uint32_t)((kh + mt) * SLAB) +
                                  (w_base + (uint32_t)kw + lrow) * 32 + lcol16;
                    ldsm_x4(ah[mt], aa);
                    ldsm_x4(al[mt], aa + AT_LO_OFF);
                }
                const uint32_t kb = (uint32_t)(ks * 32);
                uint32_t bh[4], bl[4], bh2[4], bl2[4];
                ldsm_x4(bh, b1_addr + kb);
                ldsm_x4(bl, b1_addr + kb + (SB_B1L - SB_B1H));
                ldsm_x4(bh2, b1_addr + 16 * 304 + kb);
                ldsm_x4(bl2, b1_addr + 16 * 304 + kb + (SB_B1L - SB_B1H));
#pragma unroll
                for (int mt = 0; mt < 2; ++mt) {
                    mma_bf16(ay[mt][0], ah[mt], &bh[0]);
                    mma_bf16(ay[mt][1], ah[mt], &bh[2]);
                    mma_bf16(ay[mt][2], ah[mt], &bh2[0]);
                    mma_bf16(ay[mt][0], al[mt], &bh[0]);
                    mma_bf16(ay[mt][1], al[mt], &bh[2]);
                    mma_bf16(ay[mt][2], al[mt], &bh2[0]);
                    mma_bf16(ay[mt][0], ah[mt], &bl[0]);
                    mma_bf16(ay[mt][1], ah[mt], &bl[2]);
                    mma_bf16(ay[mt][2], ah[mt], &bl2[0]);
                }
            }

            // repack feat -> bf16 hi/lo [p][48B]; p = mt*128 + w
#pragma unroll
            for (int mt = 0; mt < 2; ++mt) {
                const uint32_t p0 = (uint32_t)(mt * 128 + wid * 16 + r);
#pragma unroll
                for (int g = 0; g < 2; ++g) {
                    float y0 = ay[mt][g][0], y1 = ay[mt][g][1];
                    float y2 = ay[mt][g][2], y3 = ay[mt][g][3];
                    uint32_t h0r = cvt_bf16x2(y1, y0);
                    uint32_t h1r = cvt_bf16x2(y3, y2);
                    uint32_t l0r = cvt_bf16x2(y1 - __uint_as_float(h0r & 0xFFFF0000u),
                                              y0 - __uint_as_float(h0r << 16));
                    uint32_t l1r = cvt_bf16x2(y3 - __uint_as_float(h1r & 0xFFFF0000u),
                                              y2 - __uint_as_float(h1r << 16));
                    uint32_t off0 = p0 * 48 + (uint32_t)(g * 16 + q * 4);
                    uint32_t off1 = (p0 + 8) * 48 + (uint32_t)(g * 16 + q * 4);
                    *(uint32_t*)(sm + SB_FH + off0) = h0r;
                    *(uint32_t*)(sm + SB_FH + off1) = h1r;
                    *(uint32_t*)(sm + SB_FL + off0) = l0r;
                    *(uint32_t*)(sm + SB_FL + off1) = l1r;
                }
                if (q == 0) {
                    smf[SB_S / 4 + p0] = ay[mt][2][0];
                    smf[SB_S / 4 + p0 + 8] = ay[mt][2][2];
                }
            }
        }
        __syncthreads();

        // ============ PHASE 2: h = [feat|x] x W~ + u*s (2 m-tiles) =========
        float acc[2][8][4];
#pragma unroll
        for (int g = 0; g < 8; ++g) {
            float2 bv = *(const float2*)(smf + SB_B1F / 4 + nw2 * 64 + g * 8 + q * 2);
#pragma unroll
            for (int mt = 0; mt < 2; ++mt) {
                acc[mt][g][0] = bv.x; acc[mt][g][1] = bv.y;
                acc[mt][g][2] = bv.x; acc[mt][g][3] = bv.y;
            }
        }

        const int hrow = mw2 >> 2;
        const int wb2 = (mw2 & 3) * 32;
#pragma unroll
        for (int kst = 0; kst < 2; ++kst) {
            uint32_t ah[2][4], al[2][4];
#pragma unroll
            for (int mt = 0; mt < 2; ++mt) {
                if (kst == 0) {
                    uint32_t fa = smem_base + SB_FH +
                        ((uint32_t)(mw2 * 32 + mt * 16) + lrow) * 48 + lcol16;
                    ldsm_x4(ah[mt], fa);
                    ldsm_x4(al[mt], fa + (SB_FL - SB_FH));
                } else {
                    uint32_t xa = at_cur + (uint32_t)((1 + hrow) * SLAB) +
                        ((uint32_t)(wb2 + mt * 16 + 1) + lrow) * 32 + lcol16;
                    ldsm_x4(ah[mt], xa);
                    ldsm_x4(al[mt], xa + AT_LO_OFF);
                }
            }
            const uint32_t kb = (uint32_t)(kst * 32);
#pragma unroll
            for (int cc = 0; cc < 4; ++cc) {
                uint32_t bh[4], bl[4];
                uint32_t ba = bt_addr + (uint32_t)(cc * 16) * 80 + kb;
                ldsm_x4(bh, ba);
                ldsm_x4(bl, ba + (SB_BTL - SB_BTH));
#pragma unroll
                for (int mt = 0; mt < 2; ++mt) {
                    mma_bf16(acc[mt][2 * cc],     ah[mt], &bh[0]);
                    mma_bf16(acc[mt][2 * cc + 1], ah[mt], &bh[2]);
                    mma_bf16(acc[mt][2 * cc],     al[mt], &bh[0]);
                    mma_bf16(acc[mt][2 * cc + 1], al[mt], &bh[2]);
                    mma_bf16(acc[mt][2 * cc],     ah[mt], &bl[0]);
                    mma_bf16(acc[mt][2 * cc + 1], ah[mt], &bl[2]);
                }
            }
        }

        // rank-1 conv_x path
#pragma unroll
        for (int mt = 0; mt < 2; ++mt) {
            int pb = mw2 * 32 + mt * 16;
            float s0 = smf[SB_S / 4 + pb + r];
            float s1 = smf[SB_S / 4 + pb + r + 8];
#pragma unroll
            for (int g = 0; g < 8; ++g) {
                float2 u2 = *(const float2*)(smf + SB_U / 4 + nw2 * 64 + g * 8 + q * 2);
                acc[mt][g][0] += u2.x * s0;
                acc[mt][g][1] += u2.y * s0;
                acc[mt][g][2] += u2.x * s1;
                acc[mt][g][3] += u2.y * s1;
            }
        }

        // ============ TAIL per m-tile (sequential to cap registers) ========
#pragma unroll
        for (int mt = 0; mt < 2; ++mt) {
            float oacc[2][4];
#pragma unroll
            for (int jj = 0; jj < 2; ++jj) {
                float2 bv = *(const float2*)(smf + SB_B2 / 4 + jj * 8 + q * 2);
                float c0 = (nw2 == 0) ? bv.x : 0.f;
                float c1 = (nw2 == 0) ? bv.y : 0.f;
                oacc[jj][0] = c0; oacc[jj][1] = c1;
                oacc[jj][2] = c0; oacc[jj][3] = c1;
            }
#pragma unroll
            for (int kt = 0; kt < 4; ++kt) {
                uint32_t wh[4], wl[4];
                uint32_t wa = w2_addr + (uint32_t)(kt * 32);
                ldsm_x4(wh, wa);
                ldsm_x4(wl, wa + (SB_W2L - SB_W2H));
                float y0 = fmaxf(acc[mt][2 * kt][0], 0.f),     y1 = fmaxf(acc[mt][2 * kt][1], 0.f);
                float y2 = fmaxf(acc[mt][2 * kt][2], 0.f),     y3 = fmaxf(acc[mt][2 * kt][3], 0.f);
                float z0 = fmaxf(acc[mt][2 * kt + 1][0], 0.f), z1 = fmaxf(acc[mt][2 * kt + 1][1], 0.f);
                float z2 = fmaxf(acc[mt][2 * kt + 1][2], 0.f), z3 = fmaxf(acc[mt][2 * kt + 1][3], 0.f);
                uint32_t ah2[4], al2[4];
                ah2[0] = cvt_bf16x2(y1, y0);
                ah2[1] = cvt_bf16x2(y3, y2);
                ah2[2] = cvt_bf16x2(z1, z0);
                ah2[3] = cvt_bf16x2(z3, z2);
                al2[0] = cvt_bf16x2(y1 - __uint_as_float(ah2[0] & 0xFFFF0000u),
                                    y0 - __uint_as_float(ah2[0] << 16));
                al2[1] = cvt_bf16x2(y3 - __uint_as_float(ah2[1] & 0xFFFF0000u),
                                    y2 - __uint_as_float(ah2[1] << 16));
                al2[2] = cvt_bf16x2(z1 - __uint_as_float(ah2[2] & 0xFFFF0000u),
                                    z0 - __uint_as_float(ah2[2] << 16));
                al2[3] = cvt_bf16x2(z3 - __uint_as_float(ah2[3] & 0xFFFF0000u),
                                    z2 - __uint_as_float(ah2[3] << 16));
                mma_bf16(oacc[0], ah2, &wh[0]);
                mma_bf16(oacc[1], ah2, &wh[2]);
                mma_bf16(oacc[0], al2, &wh[0]);
                mma_bf16(oacc[1], al2, &wh[2]);
                mma_bf16(oacc[0], ah2, &wl[0]);
                mma_bf16(oacc[1], ah2, &wl[2]);
            }
            // stage this m-tile's partials
            {
                float* obuf = smf + SB_OUT / 4 + nw2 * 5120;
                int p0 = mw2 * 32 + mt * 16 + r;
                float* s0 = obuf + p0 * 20;
                float* s1 = obuf + (p0 + 8) * 20;
                *(float2*)(s0 + 2 * q)     = make_float2(oacc[0][0], oacc[0][1]);
                *(float2*)(s0 + 8 + 2 * q) = make_float2(oacc[1][0], oacc[1][1]);
                *(float2*)(s1 + 2 * q)     = make_float2(oacc[0][2], oacc[0][3]);
                *(float2*)(s1 + 8 + 2 * q) = make_float2(oacc[1][2], oacc[1][3]);
            }
        }
        __syncthreads();

        // ---- sum partials + coalesced store: 1024 float4, 2 passes ----
        {
            const float* o0 = smf + SB_OUT / 4;
#pragma unroll
            for (int t = 0; t < 2; ++t) {
                int i = tid + t * NTHREADS;
                int p = i >> 2, c4 = (i & 3) * 4;        // p in [0,256)
                int hr = p >> 7, w = p & 127;
                float4 v0 = *(const float4*)(o0 + p * 20 + c4);
                float4 v1 = *(const float4*)(o0 + 5120 + p * 20 + c4);
                float4 v = make_float4(v0.x + v1.x, v0.y + v1.y,
                                       v0.z + v1.z, v0.w + v1.w);
                long off = ((long)b << 18) + ((long)w << 11) +
                           ((long)(h0 + hr) << 4) + c4;
                *(float4*)(out + off) = v;
            }
        }
        // next iteration's top sync orders buffer reuse
    }
}

extern "C" void kernel_launch(void* const* d_in, const int* in_sizes, int n_in,
                              void* d_out, int out_size) {
    const float* x  = (const float*)d_in[0];
    const float* Wx = (const float*)d_in[1];
    const float* bx = (const float*)d_in[2];
    const float* Wy = (const float*)d_in[3];
    const float* by = (const float*)d_in[4];
    const float* W1 = (const float*)d_in[5];
    const float* b1 = (const float*)d_in[6];
    const float* W2 = (const float*)d_in[7];
    const float* b2 = (const float*)d_in[8];
    float* out = (float*)d_out;

    prep_w_kernel<<<72, 256>>>(Wx, Wy, W1, b1, bx, by, W2);
    prep_t_kernel<<<4096, 256>>>(x);

    cudaFuncSetAttribute(nca_mma_kernel,
                         cudaFuncAttributeMaxDynamicSharedMemorySize, SMEM_BYTES);
    nca_mma_kernel<<<NBLOCKS, NTHREADS, SMEM_BYTES>>>(b2, out);
}

// round 14
// speedup vs baseline: 1.7902x; 1.0191x over previous
#include <cuda_runtime.h>
#include <cuda_bf16.h>
#include <cstdint>

// ============================================================================
// out = W2 @ relu( h ) + b2,  h = [convy(x)|x] x W~  +  u*s(x)  + b1f
// s = sobel^T * xbar (xbar = sum_c x, fp32 scalar path, 9 FMA/pixel).
// Row-pair tiles (256 pixels). Phase1: feat = patch x Wy (M256 x N16 x K144),
// ALL 16 warps (M16 each). Phase2: h = [feat|x] x W~ (K32) + u*s, 8(M)x2(N).
// Tensor-core tail. bf16 2-term split, 3 cross products everywhere.
// R14 fix: xbar prefetch loop now covers all 520 elements (was tid<520 @512thr).
// ============================================================================

#define NTHREADS 512
#define PAIRS_PER_BLOCK 2
#define NBLOCKS 1024                 // 2048 pairs

// ---- SMEM byte offsets ----
#define SB_B1H   0                   // [16][304] bf16 Wy
#define SB_B1L   4864
#define SB_BTH   9728                // [128][80] bf16 W~
#define SB_BTL   19968
#define SB_W2H   30208               // [16][304]
#define SB_W2L   35072
#define SB_AT0   39936               // buf0: [prec2][slab4][130][32B] + XS
#define SB_AT1   75328
#define SB_FH    110720              // feat hi [256][48B]
#define SB_FL    123008
#define SB_S     135296              // s[256] f32
#define SB_B1F   136320              // 128 f32
#define SB_U     136832              // 128 f32
#define SB_B2    137344              // 16 f32
#define SB_SOB   137408              // 9 f32 sobel
#define SB_OUT   137472              // 2 x [256][20] f32 partials
#define SMEM_BYTES 178432
#define AT_LO_OFF 16640              // prec stride
#define SLAB 4160                    // slab stride (130*32)
#define XS_OFF 33280                 // xbar slabs offset within AT buffer

__device__ __nv_bfloat16 g_B1h[16 * 152];
__device__ __nv_bfloat16 g_B1l[16 * 152];
__device__ __nv_bfloat16 g_Bth[128 * 40];
__device__ __nv_bfloat16 g_Btl[128 * 40];
__device__ __nv_bfloat16 g_W2h[16 * 152];
__device__ __nv_bfloat16 g_W2l[16 * 152];
__device__ float g_B1f[128];
__device__ float g_u[128];
__device__ float g_sob[9];
__device__ __nv_bfloat16 g_xTh[32 * 128 * 128 * 16];
__device__ __nv_bfloat16 g_xTl[32 * 128 * 128 * 16];
__device__ float g_xSum[32 * 128 * 128];

// ---------------------------------------------------------------------------
__device__ __forceinline__ uint32_t smem_u32(const void* p) {
    uint32_t a;
    asm("{ .reg .u64 t; cvta.to.shared.u64 t, %1; cvt.u32.u64 %0, t; }" : "=r"(a) : "l"(p));
    return a;
}
__device__ __forceinline__ void ldsm_x4(uint32_t* r, uint32_t addr) {
    asm volatile("ldmatrix.sync.aligned.m8n8.x4.shared.b16 {%0,%1,%2,%3}, [%4];"
                 : "=r"(r[0]), "=r"(r[1]), "=r"(r[2]), "=r"(r[3]) : "r"(addr));
}
__device__ __forceinline__ void mma_bf16(float* c, const uint32_t* a, const uint32_t* b) {
    asm volatile("mma.sync.aligned.m16n8k16.row.col.f32.bf16.bf16.f32 "
                 "{%0,%1,%2,%3}, {%4,%5,%6,%7}, {%8,%9}, {%0,%1,%2,%3};"
                 : "+f"(c[0]), "+f"(c[1]), "+f"(c[2]), "+f"(c[3])
                 : "r"(a[0]), "r"(a[1]), "r"(a[2]), "r"(a[3]), "r"(b[0]), "r"(b[1]));
}
__device__ __forceinline__ uint32_t cvt_bf16x2(float hi, float lo) {
    uint32_t r;
    asm("cvt.rn.bf16x2.f32 %0, %1, %2;" : "=r"(r) : "f"(hi), "f"(lo));
    return r;
}
#define CP_COMMIT() asm volatile("cp.async.commit_group;" ::: "memory")
#define CP_WAIT1()  asm volatile("cp.async.wait_group 1;" ::: "memory")

// prefetch x slabs (bf16 hi/lo) + xbar slabs (f32) for a pair
__device__ __forceinline__ void prefetch_at(int pair, uint32_t at_buf, int tid) {
    const int b = pair >> 6, h0 = (pair & 63) << 1;
    for (int it = 0; it < 5; ++it) {
        int idx = tid + it * NTHREADS;
        if (idx >= 2080) break;
        int chunk = idx & 1;
        int t = idx >> 1;
        int pp = t % 130;
        int t2 = t / 130;
        int slab = t2 & 3, prec = t2 >> 2;
        int hh = h0 - 1 + slab, w = pp - 1;
        bool ok = ((unsigned)hh < 128u) && ((unsigned)w < 128u);
        const __nv_bfloat16* base = prec ? g_xTl : g_xTh;
        const __nv_bfloat16* src = base +
            ((((long)(b << 7) + (ok ? hh : 0)) << 7) + (ok ? w : 0)) * 16 + chunk * 8;
        uint32_t dst = at_buf + (uint32_t)prec * AT_LO_OFF +
                       (uint32_t)slab * SLAB + (uint32_t)pp * 32 + (uint32_t)chunk * 16;
        int sz = ok ? 16 : 0;
        asm volatile("cp.async.ca.shared.global [%0], [%1], 16, %2;"
                     :: "r"(dst), "l"(src), "r"(sz) : "memory");
    }
    // xbar slabs: 4 x 130 f32 = 520 elements -> 2 strided passes
    for (int it = 0; it < 2; ++it) {
        int idx = tid + it * NTHREADS;
        if (idx >= 520) break;
        int pp = idx % 130, slab = idx / 130;
        int hh = h0 - 1 + slab, w = pp - 1;
        bool ok = ((unsigned)hh < 128u) && ((unsigned)w < 128u);
        const float* src = g_xSum +
            ((((long)(b << 7) + (ok ? hh : 0)) << 7) + (ok ? w : 0));
        uint32_t dst = at_buf + XS_OFF + (uint32_t)(slab * 132 + pp) * 4;
        int sz = ok ? 4 : 0;
        asm volatile("cp.async.ca.shared.global [%0], [%1], 4, %2;"
                     :: "r"(dst), "l"(src), "r"(sz) : "memory");
    }
}

// ---------------------------------------------------------------------------
__global__ void prep_w_kernel(const float* __restrict__ Wx,
                              const float* __restrict__ Wy,
                              const float* __restrict__ W1,
                              const float* __restrict__ b1,
                              const float* __restrict__ bx,
                              const float* __restrict__ by,
                              const float* __restrict__ W2) {
    int idx = blockIdx.x * blockDim.x + threadIdx.x;
    if (idx < 16 * 152) {
        int o = idx / 152, k = idx - o * 152;
        float f = 0.f;
        if (k < 144) {
            int kh = k / 48, kw = (k % 48) / 16, i = k & 15;
            f = Wy[(o * 16 + i) * 9 + kh * 3 + kw];
        }
        __nv_bfloat16 hi = __float2bfloat16(f);
        __nv_bfloat16 lo = __float2bfloat16(f - __bfloat162float(hi));
        g_B1h[idx] = hi;
        g_B1l[idx] = lo;
    }
    if (idx < 128 * 40) {
        int m = idx / 40, c = idx - m * 40;
        float f = (c < 32) ? W1[m * 48 + 16 + c] : 0.f;
        __nv_bfloat16 hi = __float2bfloat16(f);
        __nv_bfloat16 lo = __float2bfloat16(f - __bfloat162float(hi));
        g_Bth[idx] = hi;
        g_Btl[idx] = lo;
    }
    if (idx < 2048) {
        int o = idx >> 7, m = idx & 127;
        float f = W2[o * 128 + m];
        __nv_bfloat16 hi = __float2bfloat16(f);
        __nv_bfloat16 lo = __float2bfloat16(f - __bfloat162float(hi));
        g_W2h[o * 152 + m] = hi;
        g_W2l[o * 152 + m] = lo;
    }
    if (idx < 9) g_sob[idx] = Wx[idx];   // tiled sobel: Wx[0,0,kh,kw]
    if (idx < 128) {
        float s = b1[idx];
        float uu = 0.f;
        const float* w1r = W1 + idx * 48;
#pragma unroll
        for (int o = 0; o < 16; ++o) {
            s += w1r[o] * bx[o] + w1r[16 + o] * by[o];
            uu += w1r[o];
        }
        g_B1f[idx] = s;
        g_u[idx] = uu;
    }
}

__global__ void prep_t_kernel(const float* __restrict__ x) {
    __shared__ float s[16 * 132];
    const int bid = blockIdx.x;
    const int b = bid >> 7, h = bid & 127;
    const int tid = threadIdx.x;
#pragma unroll
    for (int t = tid; t < 2048; t += 256) {
        int c = t >> 7, w = t & 127;
        s[c * 132 + w] = x[((b * 16 + c) << 14) + (h << 7) + w];
    }
    __syncthreads();
#pragma unroll
    for (int t = tid; t < 2048; t += 256) {
        int w = t >> 4, c = t & 15;
        float v = s[c * 132 + w];
        __nv_bfloat16 hi = __float2bfloat16(v);
        __nv_bfloat16 lo = __float2bfloat16(v - __bfloat162float(hi));
        long off = ((((long)(b << 7) + h) << 7) + w) * 16 + c;
        g_xTh[off] = hi;
        g_xTl[off] = lo;
    }
    if (tid < 128) {
        float acc = 0.f;
#pragma unroll
        for (int c = 0; c < 16; ++c) acc += s[c * 132 + tid];
        g_xSum[(((long)(b << 7) + h) << 7) + tid] = acc;
    }
}

// ---------------------------------------------------------------------------
__global__ __launch_bounds__(NTHREADS, 1)
void nca_mma_kernel(const float* __restrict__ b2g,
                    float* __restrict__ out) {
    extern __shared__ char sm[];
    float* smf = (float*)sm;
    const uint32_t smem_base = smem_u32(sm);
    const int tid = threadIdx.x;
    const int wid = tid >> 5;
    const int lane = tid & 31;
    const int q = lane & 3;
    const int r = lane >> 2;
    const int mw2 = wid & 7;
    const int nw2 = wid >> 3;
    const int pair_base = blockIdx.x * PAIRS_PER_BLOCK;

    // ---- stage persistent weights ----
    {
        uint4* d;
        const uint4* s4;
        d = (uint4*)(sm + SB_B1H); s4 = (const uint4*)g_B1h;
        for (int i = tid; i < 304; i += NTHREADS) d[i] = s4[i];
        d = (uint4*)(sm + SB_B1L); s4 = (const uint4*)g_B1l;
        for (int i = tid; i < 304; i += NTHREADS) d[i] = s4[i];
        d = (uint4*)(sm + SB_BTH); s4 = (const uint4*)g_Bth;
        for (int i = tid; i < 640; i += NTHREADS) d[i] = s4[i];
        d = (uint4*)(sm + SB_BTL); s4 = (const uint4*)g_Btl;
        for (int i = tid; i < 640; i += NTHREADS) d[i] = s4[i];
        d = (uint4*)(sm + SB_W2H); s4 = (const uint4*)g_W2h;
        for (int i = tid; i < 304; i += NTHREADS) d[i] = s4[i];
        d = (uint4*)(sm + SB_W2L); s4 = (const uint4*)g_W2l;
        for (int i = tid; i < 304; i += NTHREADS) d[i] = s4[i];
        if (tid < 128) smf[SB_B1F / 4 + tid] = g_B1f[tid];
        if (tid < 128) smf[SB_U / 4 + tid] = g_u[tid];
        if (tid < 16)  smf[SB_B2 / 4 + tid] = b2g[tid];
        if (tid < 9)   smf[SB_SOB / 4 + tid] = g_sob[tid];
    }
    prefetch_at(pair_base, smem_base + SB_AT0, tid);
    CP_COMMIT();
    __syncthreads();

    const uint32_t lrow = (uint32_t)((lane & 7) + ((lane >> 3) & 1) * 8);
    const uint32_t lcol16 = (uint32_t)((lane >> 4) * 16);
    const uint32_t brow = (uint32_t)((lane & 7) + (lane >> 4) * 8);
    const uint32_t bcol16 = (uint32_t)(((lane >> 3) & 1) * 16);

    const uint32_t b1_addr = smem_base + SB_B1H + brow * 304 + bcol16;
    const uint32_t bt_addr = smem_base + SB_BTH +
        ((uint32_t)(nw2 * 64) + brow) * 80 + bcol16;
    const uint32_t w2_addr = smem_base + SB_W2H + brow * 304 + bcol16 +
        (uint32_t)(nw2 * 128);

    // phase1 per-warp geometry (16 warps x M16)
    const int hrow1 = wid >> 3;
    const uint32_t wbase1 = (uint32_t)((wid & 7) * 16);

#pragma unroll
    for (int j = 0; j < PAIRS_PER_BLOCK; ++j) {
        const int pair = pair_base + j;
        const int b = pair >> 6;
        const int h0 = (pair & 63) << 1;
        const uint32_t at_cur = smem_base + ((j & 1) ? SB_AT1 : SB_AT0);
        const uint32_t at_nxt = smem_base + ((j & 1) ? SB_AT0 : SB_AT1);

        {
            int tn = pair + 1;
            if (tn > NBLOCKS * PAIRS_PER_BLOCK - 1) tn = NBLOCKS * PAIRS_PER_BLOCK - 1;
            prefetch_at(tn, at_nxt, tid);
            CP_COMMIT();
        }
        CP_WAIT1();
        __syncthreads();

        // ============ PHASE 1 (ALL 16 warps): feat = patch x Wy ============
        {
            float ay[2][4];
#pragma unroll
            for (int g = 0; g < 2; ++g)
#pragma unroll
                for (int e = 0; e < 4; ++e) ay[g][e] = 0.f;

#pragma unroll
            for (int ks = 0; ks < 9; ++ks) {
                const int kh = ks / 3, kw = ks - 3 * kh;
                uint32_t aa = at_cur + (uint32_t)((kh + hrow1) * SLAB) +
                              (wbase1 + (uint32_t)kw + lrow) * 32 + lcol16;
                uint32_t ah[4], al[4];
                ldsm_x4(ah, aa);
                ldsm_x4(al, aa + AT_LO_OFF);
                const uint32_t kb = (uint32_t)(ks * 32);
                uint32_t bh[4], bl[4];
                ldsm_x4(bh, b1_addr + kb);
                ldsm_x4(bl, b1_addr + kb + (SB_B1L - SB_B1H));
                mma_bf16(ay[0], ah, &bh[0]);
                mma_bf16(ay[1], ah, &bh[2]);
                mma_bf16(ay[0], al, &bh[0]);
                mma_bf16(ay[1], al, &bh[2]);
                mma_bf16(ay[0], ah, &bl[0]);
                mma_bf16(ay[1], ah, &bl[2]);
            }

            // repack feat -> bf16 hi/lo [p][48B]
            const uint32_t p0 = (uint32_t)(wid * 16 + r);
#pragma unroll
            for (int g = 0; g < 2; ++g) {
                float y0 = ay[g][0], y1 = ay[g][1], y2 = ay[g][2], y3 = ay[g][3];
                uint32_t h0r = cvt_bf16x2(y1, y0);
                uint32_t h1r = cvt_bf16x2(y3, y2);
                uint32_t l0r = cvt_bf16x2(y1 - __uint_as_float(h0r & 0xFFFF0000u),
                                          y0 - __uint_as_float(h0r << 16));
                uint32_t l1r = cvt_bf16x2(y3 - __uint_as_float(h1r & 0xFFFF0000u),
                                          y2 - __uint_as_float(h1r << 16));
                uint32_t off0 = p0 * 48 + (uint32_t)(g * 16 + q * 4);
                uint32_t off1 = (p0 + 8) * 48 + (uint32_t)(g * 16 + q * 4);
                *(uint32_t*)(sm + SB_FH + off0) = h0r;
                *(uint32_t*)(sm + SB_FH + off1) = h1r;
                *(uint32_t*)(sm + SB_FL + off0) = l0r;
                *(uint32_t*)(sm + SB_FL + off1) = l1r;
            }

            // scalar s: 9 fp32 FMA per pixel from xbar slabs
            if (tid < 256) {
                int hr = tid >> 7, wc = tid & 127;
                const float* xs = smf + (at_cur - smem_base + XS_OFF) / 4 +
                                  hr * 132 + wc;
                float sv = 0.f;
#pragma unroll
                for (int kk = 0; kk < 9; ++kk) {
                    int kh = kk / 3, kw = kk - 3 * kh;
                    sv += smf[SB_SOB / 4 + kk] * xs[kh * 132 + kw];
                }
                smf[SB_S / 4 + tid] = sv;
            }
        }
        __syncthreads();

        // ============ PHASE 2: h = [feat|x] x W~ + u*s (2 m-tiles) =========
        float acc[2][8][4];
#pragma unroll
        for (int g = 0; g < 8; ++g) {
            float2 bv = *(const float2*)(smf + SB_B1F / 4 + nw2 * 64 + g * 8 + q * 2);
#pragma unroll
            for (int mt = 0; mt < 2; ++mt) {
                acc[mt][g][0] = bv.x; acc[mt][g][1] = bv.y;
                acc[mt][g][2] = bv.x; acc[mt][g][3] = bv.y;
            }
        }

        const int hrow = mw2 >> 2;
        const int wb2 = (mw2 & 3) * 32;
#pragma unroll
        for (int kst = 0; kst < 2; ++kst) {
            uint32_t ah[2][4], al[2][4];
#pragma unroll
            for (int mt = 0; mt < 2; ++mt) {
                if (kst == 0) {
                    uint32_t fa = smem_base + SB_FH +
                        ((uint32_t)(mw2 * 32 + mt * 16) + lrow) * 48 + lcol16;
                    ldsm_x4(ah[mt], fa);
                    ldsm_x4(al[mt], fa + (SB_FL - SB_FH));
                } else {
                    uint32_t xa = at_cur + (uint32_t)((1 + hrow) * SLAB) +
                        ((uint32_t)(wb2 + mt * 16 + 1) + lrow) * 32 + lcol16;
                    ldsm_x4(ah[mt], xa);
                    ldsm_x4(al[mt], xa + AT_LO_OFF);
                }
            }
            const uint32_t kb = (uint32_t)(kst * 32);
#pragma unroll
            for (int cc = 0; cc < 4; ++cc) {
                uint32_t bh[4], bl[4];
                uint32_t ba = bt_addr + (uint32_t)(cc * 16) * 80 + kb;
                ldsm_x4(bh, ba);
                ldsm_x4(bl, ba + (SB_BTL - SB_BTH));
#pragma unroll
                for (int mt = 0; mt < 2; ++mt) {
                    mma_bf16(acc[mt][2 * cc],     ah[mt], &bh[0]);
                    mma_bf16(acc[mt][2 * cc + 1], ah[mt], &bh[2]);
                    mma_bf16(acc[mt][2 * cc],     al[mt], &bh[0]);
                    mma_bf16(acc[mt][2 * cc + 1], al[mt], &bh[2]);
                    mma_bf16(acc[mt][2 * cc],     ah[mt], &bl[0]);
                    mma_bf16(acc[mt][2 * cc + 1], ah[mt], &bl[2]);
                }
            }
        }

        // rank-1 conv_x path
#pragma unroll
        for (int mt = 0; mt < 2; ++mt) {
            int pb = mw2 * 32 + mt * 16;
            float s0 = smf[SB_S / 4 + pb + r];
            float s1 = smf[SB_S / 4 + pb + r + 8];
#pragma unroll
            for (int g = 0; g < 8; ++g) {
                float2 u2 = *(const float2*)(smf + SB_U / 4 + nw2 * 64 + g * 8 + q * 2);
                acc[mt][g][0] += u2.x * s0;
                acc[mt][g][1] += u2.y * s0;
                acc[mt][g][2] += u2.x * s1;
                acc[mt][g][3] += u2.y * s1;
            }
        }

        // ============ TAIL per m-tile ======================================
#pragma unroll
        for (int mt = 0; mt < 2; ++mt) {
            float oacc[2][4];
#pragma unroll
            for (int jj = 0; jj < 2; ++jj) {
                float2 bv = *(const float2*)(smf + SB_B2 / 4 + jj * 8 + q * 2);
                float c0 = (nw2 == 0) ? bv.x : 0.f;
                float c1 = (nw2 == 0) ? bv.y : 0.f;
                oacc[jj][0] = c0; oacc[jj][1] = c1;
                oacc[jj][2] = c0; oacc[jj][3] = c1;
            }
#pragma unroll
            for (int kt = 0; kt < 4; ++kt) {
                uint32_t wh[4], wl[4];
                uint32_t wa = w2_addr + (uint32_t)(kt * 32);
                ldsm_x4(wh, wa);
                ldsm_x4(wl, wa + (SB_W2L - SB_W2H));
                float y0 = fmaxf(acc[mt][2 * kt][0], 0.f),     y1 = fmaxf(acc[mt][2 * kt][1], 0.f);
                float y2 = fmaxf(acc[mt][2 * kt][2], 0.f),     y3 = fmaxf(acc[mt][2 * kt][3], 0.f);
                float z0 = fmaxf(acc[mt][2 * kt + 1][0], 0.f), z1 = fmaxf(acc[mt][2 * kt + 1][1], 0.f);
                float z2 = fmaxf(acc[mt][2 * kt + 1][2], 0.f), z3 = fmaxf(acc[mt][2 * kt + 1][3], 0.f);
                uint32_t ah2[4], al2[4];
                ah2[0] = cvt_bf16x2(y1, y0);
                ah2[1] = cvt_bf16x2(y3, y2);
                ah2[2] = cvt_bf16x2(z1, z0);
                ah2[3] = cvt_bf16x2(z3, z2);
                al2[0] = cvt_bf16x2(y1 - __uint_as_float(ah2[0] & 0xFFFF0000u),
                                    y0 - __uint_as_float(ah2[0] << 16));
                al2[1] = cvt_bf16x2(y3 - __uint_as_float(ah2[1] & 0xFFFF0000u),
                                    y2 - __uint_as_float(ah2[1] << 16));
                al2[2] = cvt_bf16x2(z1 - __uint_as_float(ah2[2] & 0xFFFF0000u),
                                    z0 - __uint_as_float(ah2[2] << 16));
                al2[3] = cvt_bf16x2(z3 - __uint_as_float(ah2[3] & 0xFFFF0000u),
                                    z2 - __uint_as_float(ah2[3] << 16));
                mma_bf16(oacc[0], ah2, &wh[0]);
                mma_bf16(oacc[1], ah2, &wh[2]);
                mma_bf16(oacc[0], al2, &wh[0]);
                mma_bf16(oacc[1], al2, &wh[2]);
                mma_bf16(oacc[0], ah2, &wl[0]);
                mma_bf16(oacc[1], ah2, &wl[2]);
            }
            {
                float* obuf = smf + SB_OUT / 4 + nw2 * 5120;
                int p0 = mw2 * 32 + mt * 16 + r;
                float* s0 = obuf + p0 * 20;
                float* s1 = obuf + (p0 + 8) * 20;
                *(float2*)(s0 + 2 * q)     = make_float2(oacc[0][0], oacc[0][1]);
                *(float2*)(s0 + 8 + 2 * q) = make_float2(oacc[1][0], oacc[1][1]);
                *(float2*)(s1 + 2 * q)     = make_float2(oacc[0][2], oacc[0][3]);
                *(float2*)(s1 + 8 + 2 * q) = make_float2(oacc[1][2], oacc[1][3]);
            }
        }
        __syncthreads();

        // ---- sum partials + coalesced store: 1024 float4, 2 passes ----
        {
            const float* o0 = smf + SB_OUT / 4;
#pragma unroll
            for (int t = 0; t < 2; ++t) {
                int i = tid + t * NTHREADS;
                int p = i >> 2, c4 = (i & 3) * 4;        // p in [0,256)
                int hr = p >> 7, w = p & 127;
                float4 v0 = *(const float4*)(o0 + p * 20 + c4);
                float4 v1 = *(const float4*)(o0 + 5120 + p * 20 + c4);
                float4 v = make_float4(v0.x + v1.x, v0.y + v1.y,
                                       v0.z + v1.z, v0.w + v1.w);
                long off = ((long)b << 18) + ((long)w << 11) +
                           ((long)(h0 + hr) << 4) + c4;
                *(float4*)(out + off) = v;
            }
        }
    }
}

extern "C" void kernel_launch(void* const* d_in, const int* in_sizes, int n_in,
                              void* d_out, int out_size) {
    const float* x  = (const float*)d_in[0];
    const float* Wx = (const float*)d_in[1];
    const float* bx = (const float*)d_in[2];
    const float* Wy = (const float*)d_in[3];
    const float* by = (const float*)d_in[4];
    const float* W1 = (const float*)d_in[5];
    const float* b1 = (const float*)d_in[6];
    const float* W2 = (const float*)d_in[7];
    const float* b2 = (const float*)d_in[8];
    float* out = (float*)d_out;

    prep_w_kernel<<<72, 256>>>(Wx, Wy, W1, b1, bx, by, W2);
    prep_t_kernel<<<4096, 256>>>(x);

    cudaFuncSetAttribute(nca_mma_kernel,
                         cudaFuncAttributeMaxDynamicSharedMemorySize, SMEM_BYTES);
    nca_mma_kernel<<<NBLOCKS, NTHREADS, SMEM_BYTES>>>(b2, out);
}

// round 16
// speedup vs baseline: 1.9325x; 1.0794x over previous
#include <cuda_runtime.h>
#include <cuda_bf16.h>
#include <cstdint>

// ============================================================================
// out = W2 @ relu( h ) + b2,  h = [convy(x)|x] x W~  +  u*s(x)  + b1f
// s = sobel^T * xbar (fp32 scalar path). Row-pair tiles (256 pixels).
// Phase1: feat = patch x Wy (M256 x N16 x K144), all 16 warps.
// Phase2: h = [feat|x] x W~ (K32) + u*s, 8(M)x2(N). Tensor-core tail.
// R16: AT row stride 48B (16B-aligned AND conflict-free; 40B was misaligned,
//      32B was bank-conflicted). Merged prep (2 launches). kt-outer tail.
// ============================================================================

#define NTHREADS 512
#define PAIRS_PER_BLOCK 2
#define NBLOCKS 1024                 // 2048 pairs

// ---- SMEM byte offsets ----
#define SB_B1H   0                   // [16][304] bf16 Wy
#define SB_B1L   4864
#define SB_BTH   9728                // [128][80] bf16 W~
#define SB_BTL   19968
#define SB_W2H   30208               // [16][304]
#define SB_W2L   35072
#define SB_AT0   39936               // buf: [prec2][slab4][130][48B] + XS
#define SB_AT1   91968
#define SB_FH    144000              // feat hi [256][48B]
#define SB_FL    156288
#define SB_S     168576              // s[256] f32
#define SB_B1F   169600              // 128 f32
#define SB_U     170112              // 128 f32
#define SB_B2    170624              // 16 f32
#define SB_SOB   170688              // 9 f32
#define SB_OUT   170752              // 2 x [256][20] f32 partials
#define SMEM_BYTES 211712
#define AT_LO_OFF 24960              // prec stride (4*6240)
#define SLAB 6240                    // slab stride (130*48)
#define XS_OFF 49920                 // xbar slabs offset within AT buffer

__device__ __nv_bfloat16 g_B1h[16 * 152];
__device__ __nv_bfloat16 g_B1l[16 * 152];
__device__ __nv_bfloat16 g_Bth[128 * 40];
__device__ __nv_bfloat16 g_Btl[128 * 40];
__device__ __nv_bfloat16 g_W2h[16 * 152];
__device__ __nv_bfloat16 g_W2l[16 * 152];
__device__ float g_B1f[128];
__device__ float g_u[128];
__device__ float g_sob[9];
__device__ __nv_bfloat16 g_xTh[32 * 128 * 128 * 16];
__device__ __nv_bfloat16 g_xTl[32 * 128 * 128 * 16];
__device__ float g_xSum[32 * 128 * 128];

// ---------------------------------------------------------------------------
__device__ __forceinline__ uint32_t smem_u32(const void* p) {
    uint32_t a;
    asm("{ .reg .u64 t; cvta.to.shared.u64 t, %1; cvt.u32.u64 %0, t; }" : "=r"(a) : "l"(p));
    return a;
}
__device__ __forceinline__ void ldsm_x4(uint32_t* r, uint32_t addr) {
    asm volatile("ldmatrix.sync.aligned.m8n8.x4.shared.b16 {%0,%1,%2,%3}, [%4];"
                 : "=r"(r[0]), "=r"(r[1]), "=r"(r[2]), "=r"(r[3]) : "r"(addr));
}
__device__ __forceinline__ void mma_bf16(float* c, const uint32_t* a, const uint32_t* b) {
    asm volatile("mma.sync.aligned.m16n8k16.row.col.f32.bf16.bf16.f32 "
                 "{%0,%1,%2,%3}, {%4,%5,%6,%7}, {%8,%9}, {%0,%1,%2,%3};"
                 : "+f"(c[0]), "+f"(c[1]), "+f"(c[2]), "+f"(c[3])
                 : "r"(a[0]), "r"(a[1]), "r"(a[2]), "r"(a[3]), "r"(b[0]), "r"(b[1]));
}
__device__ __forceinline__ uint32_t cvt_bf16x2(float hi, float lo) {
    uint32_t r;
    asm("cvt.rn.bf16x2.f32 %0, %1, %2;" : "=r"(r) : "f"(hi), "f"(lo));
    return r;
}
#define CP_COMMIT() asm volatile("cp.async.commit_group;" ::: "memory")
#define CP_WAIT1()  asm volatile("cp.async.wait_group 1;" ::: "memory")

// prefetch x slabs (bf16 hi/lo) + xbar slabs (f32) for a pair
__device__ __forceinline__ void prefetch_at(int pair, uint32_t at_buf, int tid) {
    const int b = pair >> 6, h0 = (pair & 63) << 1;
    for (int it = 0; it < 5; ++it) {
        int idx = tid + it * NTHREADS;
        if (idx >= 2080) break;
        int chunk = idx & 1;
        int t = idx >> 1;
        int pp = t % 130;
        int t2 = t / 130;
        int slab = t2 & 3, prec = t2 >> 2;
        int hh = h0 - 1 + slab, w = pp - 1;
        bool ok = ((unsigned)hh < 128u) && ((unsigned)w < 128u);
        const __nv_bfloat16* base = prec ? g_xTl : g_xTh;
        const __nv_bfloat16* src = base +
            ((((long)(b << 7) + (ok ? hh : 0)) << 7) + (ok ? w : 0)) * 16 + chunk * 8;
        uint32_t dst = at_buf + (uint32_t)prec * AT_LO_OFF +
                       (uint32_t)slab * SLAB + (uint32_t)pp * 48 + (uint32_t)chunk * 16;
        int sz = ok ? 16 : 0;
        asm volatile("cp.async.ca.shared.global [%0], [%1], 16, %2;"
                     :: "r"(dst), "l"(src), "r"(sz) : "memory");
    }
    // xbar slabs: 4 x 130 f32 = 520 elements -> 2 strided passes
    for (int it = 0; it < 2; ++it) {
        int idx = tid + it * NTHREADS;
        if (idx >= 520) break;
        int pp = idx % 130, slab = idx / 130;
        int hh = h0 - 1 + slab, w = pp - 1;
        bool ok = ((unsigned)hh < 128u) && ((unsigned)w < 128u);
        const float* src = g_xSum +
            ((((long)(b << 7) + (ok ? hh : 0)) << 7) + (ok ? w : 0));
        uint32_t dst = at_buf + XS_OFF + (uint32_t)(slab * 132 + pp) * 4;
        int sz = ok ? 4 : 0;
        asm volatile("cp.async.ca.shared.global [%0], [%1], 4, %2;"
                     :: "r"(dst), "l"(src), "r"(sz) : "memory");
    }
}

// ---------------------------------------------------------------------------
// merged prep: all blocks transpose one (b,h) row of x; blocks 0..19 also
// pack weights. 2 launches/call total -> ncu -s 5 profiles the main kernel.
// ---------------------------------------------------------------------------
__global__ void prep_kernel(const float* __restrict__ x,
                            const float* __restrict__ Wx,
                            const float* __restrict__ Wy,
                            const float* __restrict__ W1,
                            const float* __restrict__ b1,
                            const float* __restrict__ bx,
                            const float* __restrict__ by,
                            const float* __restrict__ W2) {
    __shared__ float s[16 * 132];
    const int bid = blockIdx.x;
    const int b = bid >> 7, h = bid & 127;
    const int tid = threadIdx.x;

    // ---- weight prep (blocks 0..19 cover idx < 5120) ----
    int idx = bid * 256 + tid;
    if (idx < 16 * 152) {
        int o = idx / 152, k = idx - o * 152;
        float f = 0.f;
        if (k < 144) {
            int kh = k / 48, kw = (k % 48) / 16, i = k & 15;
            f = Wy[(o * 16 + i) * 9 + kh * 3 + kw];
        }
        __nv_bfloat16 hi = __float2bfloat16(f);
        __nv_bfloat16 lo = __float2bfloat16(f - __bfloat162float(hi));
        g_B1h[idx] = hi;
        g_B1l[idx] = lo;
    }
    if (idx < 128 * 40) {
        int m = idx / 40, c = idx - m * 40;
        float f = (c < 32) ? W1[m * 48 + 16 + c] : 0.f;
        __nv_bfloat16 hi = __float2bfloat16(f);
        __nv_bfloat16 lo = __float2bfloat16(f - __bfloat162float(hi));
        g_Bth[idx] = hi;
        g_Btl[idx] = lo;
    }
    if (idx < 2048) {
        int o = idx >> 7, m = idx & 127;
        float f = W2[o * 128 + m];
        __nv_bfloat16 hi = __float2bfloat16(f);
        __nv_bfloat16 lo = __float2bfloat16(f - __bfloat162float(hi));
        g_W2h[o * 152 + m] = hi;
        g_W2l[o * 152 + m] = lo;
    }
    if (idx < 9) g_sob[idx] = Wx[idx];   // tiled sobel: Wx[0,0,kh,kw]
    if (idx < 128) {
        float sv = b1[idx];
        float uu = 0.f;
        const float* w1r = W1 + idx * 48;
#pragma unroll
        for (int o = 0; o < 16; ++o) {
            sv += w1r[o] * bx[o] + w1r[16 + o] * by[o];
            uu += w1r[o];
        }
        g_B1f[idx] = sv;
        g_u[idx] = uu;
    }

    // ---- x transpose + split + channel-sum for row (b,h) ----
#pragma unroll
    for (int t = tid; t < 2048; t += 256) {
        int c = t >> 7, w = t & 127;
        s[c * 132 + w] = x[((b * 16 + c) << 14) + (h << 7) + w];
    }
    __syncthreads();
#pragma unroll
    for (int t = tid; t < 2048; t += 256) {
        int w = t >> 4, c = t & 15;
        float v = s[c * 132 + w];
        __nv_bfloat16 hi = __float2bfloat16(v);
        __nv_bfloat16 lo = __float2bfloat16(v - __bfloat162float(hi));
        long off = ((((long)(b << 7) + h) << 7) + w) * 16 + c;
        g_xTh[off] = hi;
        g_xTl[off] = lo;
    }
    if (tid < 128) {
        float acc = 0.f;
#pragma unroll
        for (int c = 0; c < 16; ++c) acc += s[c * 132 + tid];
        g_xSum[(((long)(b << 7) + h) << 7) + tid] = acc;
    }
}

// ---------------------------------------------------------------------------
__global__ __launch_bounds__(NTHREADS, 1)
void nca_mma_kernel(const float* __restrict__ b2g,
                    float* __restrict__ out) {
    extern __shared__ char sm[];
    float* smf = (float*)sm;
    const uint32_t smem_base = smem_u32(sm);
    const int tid = threadIdx.x;
    const int wid = tid >> 5;
    const int lane = tid & 31;
    const int q = lane & 3;
    const int r = lane >> 2;
    const int mw2 = wid & 7;
    const int nw2 = wid >> 3;
    const int pair_base = blockIdx.x * PAIRS_PER_BLOCK;

    // ---- stage persistent weights ----
    {
        uint4* d;
        const uint4* s4;
        d = (uint4*)(sm + SB_B1H); s4 = (const uint4*)g_B1h;
        for (int i = tid; i < 304; i += NTHREADS) d[i] = s4[i];
        d = (uint4*)(sm + SB_B1L); s4 = (const uint4*)g_B1l;
        for (int i = tid; i < 304; i += NTHREADS) d[i] = s4[i];
        d = (uint4*)(sm + SB_BTH); s4 = (const uint4*)g_Bth;
        for (int i = tid; i < 640; i += NTHREADS) d[i] = s4[i];
        d = (uint4*)(sm + SB_BTL); s4 = (const uint4*)g_Btl;
        for (int i = tid; i < 640; i += NTHREADS) d[i] = s4[i];
        d = (uint4*)(sm + SB_W2H); s4 = (const uint4*)g_W2h;
        for (int i = tid; i < 304; i += NTHREADS) d[i] = s4[i];
        d = (uint4*)(sm + SB_W2L); s4 = (const uint4*)g_W2l;
        for (int i = tid; i < 304; i += NTHREADS) d[i] = s4[i];
        if (tid < 128) smf[SB_B1F / 4 + tid] = g_B1f[tid];
        if (tid < 128) smf[SB_U / 4 + tid] = g_u[tid];
        if (tid < 16)  smf[SB_B2 / 4 + tid] = b2g[tid];
        if (tid < 9)   smf[SB_SOB / 4 + tid] = g_sob[tid];
    }
    prefetch_at(pair_base, smem_base + SB_AT0, tid);
    CP_COMMIT();
    __syncthreads();

    const uint32_t lrow = (uint32_t)((lane & 7) + ((lane >> 3) & 1) * 8);
    const uint32_t lcol16 = (uint32_t)((lane >> 4) * 16);
    const uint32_t brow = (uint32_t)((lane & 7) + (lane >> 4) * 8);
    const uint32_t bcol16 = (uint32_t)(((lane >> 3) & 1) * 16);

    const uint32_t b1_addr = smem_base + SB_B1H + brow * 304 + bcol16;
    const uint32_t bt_addr = smem_base + SB_BTH +
        ((uint32_t)(nw2 * 64) + brow) * 80 + bcol16;
    const uint32_t w2_addr = smem_base + SB_W2H + brow * 304 + bcol16 +
        (uint32_t)(nw2 * 128);

    // phase1 per-warp geometry (16 warps x M16)
    const int hrow1 = wid >> 3;
    const uint32_t wbase1 = (uint32_t)((wid & 7) * 16);

    // hoist b2 fragments
    float b2i[2][2];
#pragma unroll
    for (int jj = 0; jj < 2; ++jj) {
        b2i[jj][0] = (nw2 == 0) ? smf[SB_B2 / 4 + jj * 8 + q * 2] : 0.f;
        b2i[jj][1] = (nw2 == 0) ? smf[SB_B2 / 4 + jj * 8 + q * 2 + 1] : 0.f;
    }

#pragma unroll
    for (int j = 0; j < PAIRS_PER_BLOCK; ++j) {
        const int pair = pair_base + j;
        const int b = pair >> 6;
        const int h0 = (pair & 63) << 1;
        const uint32_t at_cur = smem_base + ((j & 1) ? SB_AT1 : SB_AT0);
        const uint32_t at_nxt = smem_base + ((j & 1) ? SB_AT0 : SB_AT1);

        {
            int tn = pair + 1;
            if (tn > NBLOCKS * PAIRS_PER_BLOCK - 1) tn = NBLOCKS * PAIRS_PER_BLOCK - 1;
            prefetch_at(tn, at_nxt, tid);
            CP_COMMIT();
        }
        CP_WAIT1();
        __syncthreads();

        // ============ PHASE 1 (ALL 16 warps): feat = patch x Wy ============
        {
            float ay[2][4];
#pragma unroll
            for (int g = 0; g < 2; ++g)
#pragma unroll
                for (int e = 0; e < 4; ++e) ay[g][e] = 0.f;

#pragma unroll
            for (int ks = 0; ks < 9; ++ks) {
                const int kh = ks / 3, kw = ks - 3 * kh;
                uint32_t aa = at_cur + (uint32_t)((kh + hrow1) * SLAB) +
                              (wbase1 + (uint32_t)kw + lrow) * 48 + lcol16;
                uint32_t ah[4], al[4];
                ldsm_x4(ah, aa);
                ldsm_x4(al, aa + AT_LO_OFF);
                const uint32_t kb = (uint32_t)(ks * 32);
                uint32_t bh[4], bl[4];
                ldsm_x4(bh, b1_addr + kb);
                ldsm_x4(bl, b1_addr + kb + (SB_B1L - SB_B1H));
                mma_bf16(ay[0], ah, &bh[0]);
                mma_bf16(ay[1], ah, &bh[2]);
                mma_bf16(ay[0], al, &bh[0]);
                mma_bf16(ay[1], al, &bh[2]);
                mma_bf16(ay[0], ah, &bl[0]);
                mma_bf16(ay[1], ah, &bl[2]);
            }

            // repack feat -> bf16 hi/lo [p][48B]
            const uint32_t p0 = (uint32_t)(wid * 16 + r);
#pragma unroll
            for (int g = 0; g < 2; ++g) {
                float y0 = ay[g][0], y1 = ay[g][1], y2 = ay[g][2], y3 = ay[g][3];
                uint32_t h0r = cvt_bf16x2(y1, y0);
                uint32_t h1r = cvt_bf16x2(y3, y2);
                uint32_t l0r = cvt_bf16x2(y1 - __uint_as_float(h0r & 0xFFFF0000u),
                                          y0 - __uint_as_float(h0r << 16));
                uint32_t l1r = cvt_bf16x2(y3 - __uint_as_float(h1r & 0xFFFF0000u),
                                          y2 - __uint_as_float(h1r << 16));
                uint32_t off0 = p0 * 48 + (uint32_t)(g * 16 + q * 4);
                uint32_t off1 = (p0 + 8) * 48 + (uint32_t)(g * 16 + q * 4);
                *(uint32_t*)(sm + SB_FH + off0) = h0r;
                *(uint32_t*)(sm + SB_FH + off1) = h1r;
                *(uint32_t*)(sm + SB_FL + off0) = l0r;
                *(uint32_t*)(sm + SB_FL + off1) = l1r;
            }

            // scalar s: 9 fp32 FMA per pixel from xbar slabs
            if (tid < 256) {
                int hr = tid >> 7, wc = tid & 127;
                const float* xs = smf + (at_cur - smem_base + XS_OFF) / 4 +
                                  hr * 132 + wc;
                float sv = 0.f;
#pragma unroll
                for (int kk = 0; kk < 9; ++kk) {
                    int kh = kk / 3, kw = kk - 3 * kh;
                    sv += smf[SB_SOB / 4 + kk] * xs[kh * 132 + kw];
                }
                smf[SB_S / 4 + tid] = sv;
            }
        }
        __syncthreads();

        // ============ PHASE 2: h = [feat|x] x W~ + u*s (2 m-tiles) =========
        float acc[2][8][4];
#pragma unroll
        for (int g = 0; g < 8; ++g) {
            float2 bv = *(const float2*)(smf + SB_B1F / 4 + nw2 * 64 + g * 8 + q * 2);
#pragma unroll
            for (int mt = 0; mt < 2; ++mt) {
                acc[mt][g][0] = bv.x; acc[mt][g][1] = bv.y;
                acc[mt][g][2] = bv.x; acc[mt][g][3] = bv.y;
            }
        }

        const int hrow = mw2 >> 2;
        const int wb2 = (mw2 & 3) * 32;
#pragma unroll
        for (int kst = 0; kst < 2; ++kst) {
            uint32_t ah[2][4], al[2][4];
#pragma unroll
            for (int mt = 0; mt < 2; ++mt) {
                if (kst == 0) {
                    uint32_t fa = smem_base + SB_FH +
                        ((uint32_t)(mw2 * 32 + mt * 16) + lrow) * 48 + lcol16;
                    ldsm_x4(ah[mt], fa);
                    ldsm_x4(al[mt], fa + (SB_FL - SB_FH));
                } else {
                    uint32_t xa = at_cur + (uint32_t)((1 + hrow) * SLAB) +
                        ((uint32_t)(wb2 + mt * 16 + 1) + lrow) * 48 + lcol16;
                    ldsm_x4(ah[mt], xa);
                    ldsm_x4(al[mt], xa + AT_LO_OFF);
                }
            }
            const uint32_t kb = (uint32_t)(kst * 32);
#pragma unroll
            for (int cc = 0; cc < 4; ++cc) {
                uint32_t bh[4], bl[4];
                uint32_t ba = bt_addr + (uint32_t)(cc * 16) * 80 + kb;
                ldsm_x4(bh, ba);
                ldsm_x4(bl, ba + (SB_BTL - SB_BTH));
#pragma unroll
                for (int mt = 0; mt < 2; ++mt) {
                    mma_bf16(acc[mt][2 * cc],     ah[mt], &bh[0]);
                    mma_bf16(acc[mt][2 * cc + 1], ah[mt], &bh[2]);
                    mma_bf16(acc[mt][2 * cc],     al[mt], &bh[0]);
                    mma_bf16(acc[mt][2 * cc + 1], al[mt], &bh[2]);
                    mma_bf16(acc[mt][2 * cc],     ah[mt], &bl[0]);
                    mma_bf16(acc[mt][2 * cc + 1], ah[mt], &bl[2]);
                }
            }
        }

        // rank-1 conv_x path
#pragma unroll
        for (int mt = 0; mt < 2; ++mt) {
            int pb = mw2 * 32 + mt * 16;
            float s0 = smf[SB_S / 4 + pb + r];
            float s1 = smf[SB_S / 4 + pb + r + 8];
#pragma unroll
            for (int g = 0; g < 8; ++g) {
                float2 u2 = *(const float2*)(smf + SB_U / 4 + nw2 * 64 + g * 8 + q * 2);
                acc[mt][g][0] += u2.x * s0;
                acc[mt][g][1] += u2.y * s0;
                acc[mt][g][2] += u2.x * s1;
                acc[mt][g][3] += u2.y * s1;
            }
        }

        // ============ TAIL (kt-outer: W2 fragments loaded once) ============
        float oacc[2][2][4];
#pragma unroll
        for (int mt = 0; mt < 2; ++mt)
#pragma unroll
            for (int jj = 0; jj < 2; ++jj) {
                oacc[mt][jj][0] = b2i[jj][0]; oacc[mt][jj][1] = b2i[jj][1];
                oacc[mt][jj][2] = b2i[jj][0]; oacc[mt][jj][3] = b2i[jj][1];
            }

#pragma unroll
        for (int kt = 0; kt < 4; ++kt) {
            uint32_t wh[4], wl[4];
            uint32_t wa = w2_addr + (uint32_t)(kt * 32);
            ldsm_x4(wh, wa);
            ldsm_x4(wl, wa + (SB_W2L - SB_W2H));
#pragma unroll
            for (int mt = 0; mt < 2; ++mt) {
                float y0 = fmaxf(acc[mt][2 * kt][0], 0.f),     y1 = fmaxf(acc[mt][2 * kt][1], 0.f);
                float y2 = fmaxf(acc[mt][2 * kt][2], 0.f),     y3 = fmaxf(acc[mt][2 * kt][3], 0.f);
                float z0 = fmaxf(acc[mt][2 * kt + 1][0], 0.f), z1 = fmaxf(acc[mt][2 * kt + 1][1], 0.f);
                float z2 = fmaxf(acc[mt][2 * kt + 1][2], 0.f), z3 = fmaxf(acc[mt][2 * kt + 1][3], 0.f);
                uint32_t ah2[4], al2[4];
                ah2[0] = cvt_bf16x2(y1, y0);
                ah2[1] = cvt_bf16x2(y3, y2);
                ah2[2] = cvt_bf16x2(z1, z0);
                ah2[3] = cvt_bf16x2(z3, z2);
                al2[0] = cvt_bf16x2(y1 - __uint_as_float(ah2[0] & 0xFFFF0000u),
                                    y0 - __uint_as_float(ah2[0] << 16));
                al2[1] = cvt_bf16x2(y3 - __uint_as_float(ah2[1] & 0xFFFF0000u),
                                    y2 - __uint_as_float(ah2[1] << 16));
                al2[2] = cvt_bf16x2(z1 - __uint_as_float(ah2[2] & 0xFFFF0000u),
                                    z0 - __uint_as_float(ah2[2] << 16));
                al2[3] = cvt_bf16x2(z3 - __uint_as_float(ah2[3] & 0xFFFF0000u),
                                    z2 - __uint_as_float(ah2[3] << 16));
                mma_bf16(oacc[mt][0], ah2, &wh[0]);
                mma_bf16(oacc[mt][1], ah2, &wh[2]);
                mma_bf16(oacc[mt][0], al2, &wh[0]);
                mma_bf16(oacc[mt][1], al2, &wh[2]);
                mma_bf16(oacc[mt][0], ah2, &wl[0]);
                mma_bf16(oacc[mt][1], ah2, &wl[2]);
            }
        }

        // ---- stage 2 partial buffers by nw2 ----
#pragma unroll
        for (int mt = 0; mt < 2; ++mt) {
            float* obuf = smf + SB_OUT / 4 + nw2 * 5120;
            int p0 = mw2 * 32 + mt * 16 + r;
            float* s0 = obuf + p0 * 20;
            float* s1 = obuf + (p0 + 8) * 20;
            *(float2*)(s0 + 2 * q)     = make_float2(oacc[mt][0][0], oacc[mt][0][1]);
            *(float2*)(s0 + 8 + 2 * q) = make_float2(oacc[mt][1][0], oacc[mt][1][1]);
            *(float2*)(s1 + 2 * q)     = make_float2(oacc[mt][0][2], oacc[mt][0][3]);
            *(float2*)(s1 + 8 + 2 * q) = make_float2(oacc[mt][1][2], oacc[mt][1][3]);
        }
        __syncthreads();

        // ---- sum partials + coalesced store: 1024 float4, 2 passes ----
        {
            const float* o0 = smf + SB_OUT / 4;
#pragma unroll
            for (int t = 0; t < 2; ++t) {
                int i = tid + t * NTHREADS;
                int p = i >> 2, c4 = (i & 3) * 4;        // p in [0,256)
                int hr = p >> 7, w = p & 127;
                float4 v0 = *(const float4*)(o0 + p * 20 + c4);
                float4 v1 = *(const float4*)(o0 + 5120 + p * 20 + c4);
                float4 v = make_float4(v0.x + v1.x, v0.y + v1.y,
                                       v0.z + v1.z, v0.w + v1.w);
                long off = ((long)b << 18) + ((long)w << 11) +
                           ((long)(h0 + hr) << 4) + c4;
                *(float4*)(out + off) = v;
            }
        }
    }
}

extern "C" void kernel_launch(void* const* d_in, const int* in_sizes, int n_in,
                              void* d_out, int out_size) {
    const float* x  = (const float*)d_in[0];
    const float* Wx = (const float*)d_in[1];
    const float* bx = (const float*)d_in[2];
    const float* Wy = (const float*)d_in[3];
    const float* by = (const float*)d_in[4];
    const float* W1 = (const float*)d_in[5];
    const float* b1 = (const float*)d_in[6];
    const float* W2 = (const float*)d_in[7];
    const float* b2 = (const float*)d_in[8];
    float* out = (float*)d_out;

    prep_kernel<<<4096, 256>>>(x, Wx, Wy, W1, b1, bx, by, W2);

    cudaFuncSetAttribute(nca_mma_kernel,
                         cudaFuncAttributeMaxDynamicSharedMemorySize, SMEM_BYTES);
    nca_mma_kernel<<<NBLOCKS, NTHREADS, SMEM_BYTES>>>(b2, out);
}

// round 17
// speedup vs baseline: 1.9915x; 1.0306x over previous
#include <cuda_runtime.h>
#include <cuda_bf16.h>
#include <cstdint>

// ============================================================================
// out = W2 @ relu( h ) + b2,  h = [convy(x)|x] x W~  +  u*s(x)  + b1f
// s = sobel^T * xbar (fp32 scalar path). Row-pair tiles (256 pixels).
// Phase1: feat = patch x Wy (M256 x N16 x K144), all 16 warps.
// Phase2: h = [feat|x] x W~ (K32) + u*s, 8(M)x2(N). Tensor-core tail.
// R17: halo rows pre-zeroed once; prefetch is pure shift/mask addressing
//      (no div/mod), 2048+512 coalesced cp.asyncs per pair.
// ============================================================================

#define NTHREADS 512
#define PAIRS_PER_BLOCK 2
#define NBLOCKS 1024                 // 2048 pairs

// ---- SMEM byte offsets ----
#define SB_B1H   0                   // [16][304] bf16 Wy
#define SB_B1L   4864
#define SB_BTH   9728                // [128][80] bf16 W~
#define SB_BTL   19968
#define SB_W2H   30208               // [16][304]
#define SB_W2L   35072
#define SB_AT0   39936               // buf: [prec2][slab4][130][48B] + XS
#define SB_AT1   91968
#define SB_FH    144000              // feat hi [256][48B]
#define SB_FL    156288
#define SB_S     168576              // s[256] f32
#define SB_B1F   169600              // 128 f32
#define SB_U     170112              // 128 f32
#define SB_B2    170624              // 16 f32
#define SB_SOB   170688              // 9 f32
#define SB_OUT   170752              // 2 x [256][20] f32 partials
#define SMEM_BYTES 211712
#define AT_LO_OFF 24960              // prec stride (4*6240)
#define SLAB 6240                    // slab stride (130*48)
#define XS_OFF 49920                 // xbar slabs offset within AT buffer

__device__ __nv_bfloat16 g_B1h[16 * 152];
__device__ __nv_bfloat16 g_B1l[16 * 152];
__device__ __nv_bfloat16 g_Bth[128 * 40];
__device__ __nv_bfloat16 g_Btl[128 * 40];
__device__ __nv_bfloat16 g_W2h[16 * 152];
__device__ __nv_bfloat16 g_W2l[16 * 152];
__device__ float g_B1f[128];
__device__ float g_u[128];
__device__ float g_sob[9];
__device__ __nv_bfloat16 g_xTh[32 * 128 * 128 * 16];
__device__ __nv_bfloat16 g_xTl[32 * 128 * 128 * 16];
__device__ float g_xSum[32 * 128 * 128];

// ---------------------------------------------------------------------------
__device__ __forceinline__ uint32_t smem_u32(const void* p) {
    uint32_t a;
    asm("{ .reg .u64 t; cvta.to.shared.u64 t, %1; cvt.u32.u64 %0, t; }" : "=r"(a) : "l"(p));
    return a;
}
__device__ __forceinline__ void ldsm_x4(uint32_t* r, uint32_t addr) {
    asm volatile("ldmatrix.sync.aligned.m8n8.x4.shared.b16 {%0,%1,%2,%3}, [%4];"
                 : "=r"(r[0]), "=r"(r[1]), "=r"(r[2]), "=r"(r[3]) : "r"(addr));
}
__device__ __forceinline__ void mma_bf16(float* c, const uint32_t* a, const uint32_t* b) {
    asm volatile("mma.sync.aligned.m16n8k16.row.col.f32.bf16.bf16.f32 "
                 "{%0,%1,%2,%3}, {%4,%5,%6,%7}, {%8,%9}, {%0,%1,%2,%3};"
                 : "+f"(c[0]), "+f"(c[1]), "+f"(c[2]), "+f"(c[3])
                 : "r"(a[0]), "r"(a[1]), "r"(a[2]), "r"(a[3]), "r"(b[0]), "r"(b[1]));
}
__device__ __forceinline__ uint32_t cvt_bf16x2(float hi, float lo) {
    uint32_t r;
    asm("cvt.rn.bf16x2.f32 %0, %1, %2;" : "=r"(r) : "f"(hi), "f"(lo));
    return r;
}
#define CP_COMMIT() asm volatile("cp.async.commit_group;" ::: "memory")
#define CP_WAIT1()  asm volatile("cp.async.wait_group 1;" ::: "memory")

// prefetch interior x slabs (bf16 hi/lo) + xbar slabs (f32): pure shift/mask
__device__ __forceinline__ void prefetch_at(int pair, uint32_t at_buf, int tid) {
    const int b = pair >> 6, h0 = (pair & 63) << 1;
    const long rowbase = (long)(b << 7);
#pragma unroll
    for (int it = 0; it < 4; ++it) {
        int idx = tid + it * NTHREADS;      // 0..2047
        int chunk = idx & 1;
        int w = (idx >> 1) & 127;
        int slab = (idx >> 8) & 3;
        int prec = idx >> 10;
        int hh = h0 - 1 + slab;
        bool ok = (unsigned)hh < 128u;
        const __nv_bfloat16* base = prec ? g_xTl : g_xTh;
        const __nv_bfloat16* src = base +
            (((rowbase + (ok ? hh : 0)) << 7) + w) * 16 + chunk * 8;
        uint32_t dst = at_buf + (uint32_t)prec * AT_LO_OFF +
                       (uint32_t)slab * SLAB + (uint32_t)(w + 1) * 48 +
                       (uint32_t)chunk * 16;
        int sz = ok ? 16 : 0;
        asm volatile("cp.async.ca.shared.global [%0], [%1], 16, %2;"
                     :: "r"(dst), "l"(src), "r"(sz) : "memory");
    }
    {
        int w = tid & 127, slab = tid >> 7;  // 512 = exactly one pass
        int hh = h0 - 1 + slab;
        bool ok = (unsigned)hh < 128u;
        const float* src = g_xSum + ((rowbase + (ok ? hh : 0)) << 7) + w;
        uint32_t dst = at_buf + XS_OFF + (uint32_t)(slab * 132 + w + 1) * 4;
        int sz = ok ? 4 : 0;
        asm volatile("cp.async.ca.shared.global [%0], [%1], 4, %2;"
                     :: "r"(dst), "l"(src), "r"(sz) : "memory");
    }
}

// ---------------------------------------------------------------------------
// merged prep: all blocks transpose one (b,h) row of x; blocks 0..19 also
// pack weights. 2 launches/call total.
// ---------------------------------------------------------------------------
__global__ void prep_kernel(const float* __restrict__ x,
                            const float* __restrict__ Wx,
                            const float* __restrict__ Wy,
                            const float* __restrict__ W1,
                            const float* __restrict__ b1,
                            const float* __restrict__ bx,
                            const float* __restrict__ by,
                            const float* __restrict__ W2) {
    __shared__ float s[16 * 132];
    const int bid = blockIdx.x;
    const int b = bid >> 7, h = bid & 127;
    const int tid = threadIdx.x;

    int idx = bid * 256 + tid;
    if (idx < 16 * 152) {
        int o = idx / 152, k = idx - o * 152;
        float f = 0.f;
        if (k < 144) {
            int kh = k / 48, kw = (k % 48) / 16, i = k & 15;
            f = Wy[(o * 16 + i) * 9 + kh * 3 + kw];
        }
        __nv_bfloat16 hi = __float2bfloat16(f);
        __nv_bfloat16 lo = __float2bfloat16(f - __bfloat162float(hi));
        g_B1h[idx] = hi;
        g_B1l[idx] = lo;
    }
    if (idx < 128 * 40) {
        int m = idx / 40, c = idx - m * 40;
        float f = (c < 32) ? W1[m * 48 + 16 + c] : 0.f;
        __nv_bfloat16 hi = __float2bfloat16(f);
        __nv_bfloat16 lo = __float2bfloat16(f - __bfloat162float(hi));
        g_Bth[idx] = hi;
        g_Btl[idx] = lo;
    }
    if (idx < 2048) {
        int o = idx >> 7, m = idx & 127;
        float f = W2[o * 128 + m];
        __nv_bfloat16 hi = __float2bfloat16(f);
        __nv_bfloat16 lo = __float2bfloat16(f - __bfloat162float(hi));
        g_W2h[o * 152 + m] = hi;
        g_W2l[o * 152 + m] = lo;
    }
    if (idx < 9) g_sob[idx] = Wx[idx];
    if (idx < 128) {
        float sv = b1[idx];
        float uu = 0.f;
        const float* w1r = W1 + idx * 48;
#pragma unroll
        for (int o = 0; o < 16; ++o) {
            sv += w1r[o] * bx[o] + w1r[16 + o] * by[o];
            uu += w1r[o];
        }
        g_B1f[idx] = sv;
        g_u[idx] = uu;
    }

#pragma unroll
    for (int t = tid; t < 2048; t += 256) {
        int c = t >> 7, w = t & 127;
        s[c * 132 + w] = x[((b * 16 + c) << 14) + (h << 7) + w];
    }
    __syncthreads();
#pragma unroll
    for (int t = tid; t < 2048; t += 256) {
        int w = t >> 4, c = t & 15;
        float v = s[c * 132 + w];
        __nv_bfloat16 hi = __float2bfloat16(v);
        __nv_bfloat16 lo = __float2bfloat16(v - __bfloat162float(hi));
        long off = ((((long)(b << 7) + h) << 7) + w) * 16 + c;
        g_xTh[off] = hi;
        g_xTl[off] = lo;
    }
    if (tid < 128) {
        float acc = 0.f;
#pragma unroll
        for (int c = 0; c < 16; ++c) acc += s[c * 132 + tid];
        g_xSum[(((long)(b << 7) + h) << 7) + tid] = acc;
    }
}

// ---------------------------------------------------------------------------
__global__ __launch_bounds__(NTHREADS, 1)
void nca_mma_kernel(const float* __restrict__ b2g,
                    float* __restrict__ out) {
    extern __shared__ char sm[];
    float* smf = (float*)sm;
    const uint32_t smem_base = smem_u32(sm);
    const int tid = threadIdx.x;
    const int wid = tid >> 5;
    const int lane = tid & 31;
    const int q = lane & 3;
    const int r = lane >> 2;
    const int mw2 = wid & 7;
    const int nw2 = wid >> 3;
    const int pair_base = blockIdx.x * PAIRS_PER_BLOCK;

    // ---- stage persistent weights ----
    {
        uint4* d;
        const uint4* s4;
        d = (uint4*)(sm + SB_B1H); s4 = (const uint4*)g_B1h;
        for (int i = tid; i < 304; i += NTHREADS) d[i] = s4[i];
        d = (uint4*)(sm + SB_B1L); s4 = (const uint4*)g_B1l;
        for (int i = tid; i < 304; i += NTHREADS) d[i] = s4[i];
        d = (uint4*)(sm + SB_BTH); s4 = (const uint4*)g_Bth;
        for (int i = tid; i < 640; i += NTHREADS) d[i] = s4[i];
        d = (uint4*)(sm + SB_BTL); s4 = (const uint4*)g_Btl;
        for (int i = tid; i < 640; i += NTHREADS) d[i] = s4[i];
        d = (uint4*)(sm + SB_W2H); s4 = (const uint4*)g_W2h;
        for (int i = tid; i < 304; i += NTHREADS) d[i] = s4[i];
        d = (uint4*)(sm + SB_W2L); s4 = (const uint4*)g_W2l;
        for (int i = tid; i < 304; i += NTHREADS) d[i] = s4[i];
        if (tid < 128) smf[SB_B1F / 4 + tid] = g_B1f[tid];
        if (tid < 128) smf[SB_U / 4 + tid] = g_u[tid];
        if (tid < 16)  smf[SB_B2 / 4 + tid] = b2g[tid];
        if (tid < 9)   smf[SB_SOB / 4 + tid] = g_sob[tid];
    }

    // ---- one-time zero of constant w-halo rows (pp=0,129) in both buffers ----
    for (int i = tid; i < 384; i += NTHREADS) {
        int word = i % 12;
        int rrow = i / 12;                    // 0..31
        int halo = rrow & 1;                  // 0 -> pp=0, 1 -> pp=129
        int slab = (rrow >> 1) & 3;
        int prec = (rrow >> 3) & 1;
        int buf  = rrow >> 4;
        uint32_t off = (buf ? SB_AT1 : SB_AT0) + (uint32_t)prec * AT_LO_OFF +
                       (uint32_t)slab * SLAB + (halo ? 129u * 48u : 0u) +
                       (uint32_t)word * 4;
        *(uint32_t*)(sm + off) = 0u;
    }
    if (tid < 32) {
        int c = tid & 3;                      // 0,129,130,131
        int slab = (tid >> 2) & 3;
        int buf = tid >> 4;
        int col = c ? 128 + c : 0;
        uint32_t off = (buf ? SB_AT1 : SB_AT0) + XS_OFF +
                       (uint32_t)(slab * 132 + col) * 4;
        *(uint32_t*)(sm + off) = 0u;
    }

    prefetch_at(pair_base, smem_base + SB_AT0, tid);
    CP_COMMIT();
    __syncthreads();

    const uint32_t lrow = (uint32_t)((lane & 7) + ((lane >> 3) & 1) * 8);
    const uint32_t lcol16 = (uint32_t)((lane >> 4) * 16);
    const uint32_t brow = (uint32_t)((lane & 7) + (lane >> 4) * 8);
    const uint32_t bcol16 = (uint32_t)(((lane >> 3) & 1) * 16);

    const uint32_t b1_addr = smem_base + SB_B1H + brow * 304 + bcol16;
    const uint32_t bt_addr = smem_base + SB_BTH +
        ((uint32_t)(nw2 * 64) + brow) * 80 + bcol16;
    const uint32_t w2_addr = smem_base + SB_W2H + brow * 304 + bcol16 +
        (uint32_t)(nw2 * 128);

    const int hrow1 = wid >> 3;
    const uint32_t wbase1 = (uint32_t)((wid & 7) * 16);

    float b2i[2][2];
#pragma unroll
    for (int jj = 0; jj < 2; ++jj) {
        b2i[jj][0] = (nw2 == 0) ? smf[SB_B2 / 4 + jj * 8 + q * 2] : 0.f;
        b2i[jj][1] = (nw2 == 0) ? smf[SB_B2 / 4 + jj * 8 + q * 2 + 1] : 0.f;
    }

#pragma unroll
    for (int j = 0; j < PAIRS_PER_BLOCK; ++j) {
        const int pair = pair_base + j;
        const int b = pair >> 6;
        const int h0 = (pair & 63) << 1;
        const uint32_t at_cur = smem_base + ((j & 1) ? SB_AT1 : SB_AT0);
        const uint32_t at_nxt = smem_base + ((j & 1) ? SB_AT0 : SB_AT1);

        {
            int tn = pair + 1;
            if (tn > NBLOCKS * PAIRS_PER_BLOCK - 1) tn = NBLOCKS * PAIRS_PER_BLOCK - 1;
            prefetch_at(tn, at_nxt, tid);
            CP_COMMIT();
        }
        CP_WAIT1();
        __syncthreads();

        // ============ PHASE 1 (ALL 16 warps): feat = patch x Wy ============
        {
            float ay[2][4];
#pragma unroll
            for (int g = 0; g < 2; ++g)
#pragma unroll
                for (int e = 0; e < 4; ++e) ay[g][e] = 0.f;

#pragma unroll
            for (int ks = 0; ks < 9; ++ks) {
                const int kh = ks / 3, kw = ks - 3 * kh;
                uint32_t aa = at_cur + (uint32_t)((kh + hrow1) * SLAB) +
                              (wbase1 + (uint32_t)kw + lrow) * 48 + lcol16;
                uint32_t ah[4], al[4];
                ldsm_x4(ah, aa);
                ldsm_x4(al, aa + AT_LO_OFF);
                const uint32_t kb = (uint32_t)(ks * 32);
                uint32_t bh[4], bl[4];
                ldsm_x4(bh, b1_addr + kb);
                ldsm_x4(bl, b1_addr + kb + (SB_B1L - SB_B1H));
                mma_bf16(ay[0], ah, &bh[0]);
                mma_bf16(ay[1], ah, &bh[2]);
                mma_bf16(ay[0], al, &bh[0]);
                mma_bf16(ay[1], al, &bh[2]);
                mma_bf16(ay[0], ah, &bl[0]);
                mma_bf16(ay[1], ah, &bl[2]);
            }

            // repack feat -> bf16 hi/lo [p][48B]
            const uint32_t p0 = (uint32_t)(wid * 16 + r);
#pragma unroll
            for (int g = 0; g < 2; ++g) {
                float y0 = ay[g][0], y1 = ay[g][1], y2 = ay[g][2], y3 = ay[g][3];
                uint32_t h0r = cvt_bf16x2(y1, y0);
                uint32_t h1r = cvt_bf16x2(y3, y2);
                uint32_t l0r = cvt_bf16x2(y1 - __uint_as_float(h0r & 0xFFFF0000u),
                                          y0 - __uint_as_float(h0r << 16));
                uint32_t l1r = cvt_bf16x2(y3 - __uint_as_float(h1r & 0xFFFF0000u),
                                          y2 - __uint_as_float(h1r << 16));
                uint32_t off0 = p0 * 48 + (uint32_t)(g * 16 + q * 4);
                uint32_t off1 = (p0 + 8) * 48 + (uint32_t)(g * 16 + q * 4);
                *(uint32_t*)(sm + SB_FH + off0) = h0r;
                *(uint32_t*)(sm + SB_FH + off1) = h1r;
                *(uint32_t*)(sm + SB_FL + off0) = l0r;
                *(uint32_t*)(sm + SB_FL + off1) = l1r;
            }

            // scalar s: 9 fp32 FMA per pixel from xbar slabs
            if (tid < 256) {
                int hr = tid >> 7, wc = tid & 127;
                const float* xs = smf + (at_cur - smem_base + XS_OFF) / 4 +
                                  hr * 132 + wc;
                float sv = 0.f;
#pragma unroll
                for (int kk = 0; kk < 9; ++kk) {
                    int kh = kk / 3, kw = kk - 3 * kh;
                    sv += smf[SB_SOB / 4 + kk] * xs[kh * 132 + kw];
                }
                smf[SB_S / 4 + tid] = sv;
            }
        }
        __syncthreads();

        // ============ PHASE 2: h = [feat|x] x W~ + u*s (2 m-tiles) =========
        float acc[2][8][4];
#pragma unroll
        for (int g = 0; g < 8; ++g) {
            float2 bv = *(const float2*)(smf + SB_B1F / 4 + nw2 * 64 + g * 8 + q * 2);
#pragma unroll
            for (int mt = 0; mt < 2; ++mt) {
                acc[mt][g][0] = bv.x; acc[mt][g][1] = bv.y;
                acc[mt][g][2] = bv.x; acc[mt][g][3] = bv.y;
            }
        }

        const int hrow = mw2 >> 2;
        const int wb2 = (mw2 & 3) * 32;
#pragma unroll
        for (int kst = 0; kst < 2; ++kst) {
            uint32_t ah[2][4], al[2][4];
#pragma unroll
            for (int mt = 0; mt < 2; ++mt) {
                if (kst == 0) {
                    uint32_t fa = smem_base + SB_FH +
                        ((uint32_t)(mw2 * 32 + mt * 16) + lrow) * 48 + lcol16;
                    ldsm_x4(ah[mt], fa);
                    ldsm_x4(al[mt], fa + (SB_FL - SB_FH));
                } else {
                    uint32_t xa = at_cur + (uint32_t)((1 + hrow) * SLAB) +
                        ((uint32_t)(wb2 + mt * 16 + 1) + lrow) * 48 + lcol16;
                    ldsm_x4(ah[mt], xa);
                    ldsm_x4(al[mt], xa + AT_LO_OFF);
                }
            }
            const uint32_t kb = (uint32_t)(kst * 32);
#pragma unroll
            for (int cc = 0; cc < 4; ++cc) {
                uint32_t bh[4], bl[4];
                uint32_t ba = bt_addr + (uint32_t)(cc * 16) * 80 + kb;
                ldsm_x4(bh, ba);
                ldsm_x4(bl, ba + (SB_BTL - SB_BTH));
#pragma unroll
                for (int mt = 0; mt < 2; ++mt) {
                    mma_bf16(acc[mt][2 * cc],     ah[mt], &bh[0]);
                    mma_bf16(acc[mt][2 * cc + 1], ah[mt], &bh[2]);
                    mma_bf16(acc[mt][2 * cc],     al[mt], &bh[0]);
                    mma_bf16(acc[mt][2 * cc + 1], al[mt], &bh[2]);
                    mma_bf16(acc[mt][2 * cc],     ah[mt], &bl[0]);
                    mma_bf16(acc[mt][2 * cc + 1], ah[mt], &bl[2]);
                }
            }
        }

        // rank-1 conv_x path
#pragma unroll
        for (int mt = 0; mt < 2; ++mt) {
            int pb = mw2 * 32 + mt * 16;
            float s0 = smf[SB_S / 4 + pb + r];
            float s1 = smf[SB_S / 4 + pb + r + 8];
#pragma unroll
            for (int g = 0; g < 8; ++g) {
                float2 u2 = *(const float2*)(smf + SB_U / 4 + nw2 * 64 + g * 8 + q * 2);
                acc[mt][g][0] += u2.x * s0;
                acc[mt][g][1] += u2.y * s0;
                acc[mt][g][2] += u2.x * s1;
                acc[mt][g][3] += u2.y * s1;
            }
        }

        // ============ TAIL (kt-outer: W2 fragments loaded once) ============
        float oacc[2][2][4];
#pragma unroll
        for (int mt = 0; mt < 2; ++mt)
#pragma unroll
            for (int jj = 0; jj < 2; ++jj) {
                oacc[mt][jj][0] = b2i[jj][0]; oacc[mt][jj][1] = b2i[jj][1];
                oacc[mt][jj][2] = b2i[jj][0]; oacc[mt][jj][3] = b2i[jj][1];
            }

#pragma unroll
        for (int kt = 0; kt < 4; ++kt) {
            uint32_t wh[4], wl[4];
            uint32_t wa = w2_addr + (uint32_t)(kt * 32);
            ldsm_x4(wh, wa);
            ldsm_x4(wl, wa + (SB_W2L - SB_W2H));
#pragma unroll
            for (int mt = 0; mt < 2; ++mt) {
                float y0 = fmaxf(acc[mt][2 * kt][0], 0.f),     y1 = fmaxf(acc[mt][2 * kt][1], 0.f);
                float y2 = fmaxf(acc[mt][2 * kt][2], 0.f),     y3 = fmaxf(acc[mt][2 * kt][3], 0.f);
                float z0 = fmaxf(acc[mt][2 * kt + 1][0], 0.f), z1 = fmaxf(acc[mt][2 * kt + 1][1], 0.f);
                float z2 = fmaxf(acc[mt][2 * kt + 1][2], 0.f), z3 = fmaxf(acc[mt][2 * kt + 1][3], 0.f);
                uint32_t ah2[4], al2[4];
                ah2[0] = cvt_bf16x2(y1, y0);
                ah2[1] = cvt_bf16x2(y3, y2);
                ah2[2] = cvt_bf16x2(z1, z0);
                ah2[3] = cvt_bf16x2(z3, z2);
                al2[0] = cvt_bf16x2(y1 - __uint_as_float(ah2[0] & 0xFFFF0000u),
                                    y0 - __uint_as_float(ah2[0] << 16));
                al2[1] = cvt_bf16x2(y3 - __uint_as_float(ah2[1] & 0xFFFF0000u),
                                    y2 - __uint_as_float(ah2[1] << 16));
                al2[2] = cvt_bf16x2(z1 - __uint_as_float(ah2[2] & 0xFFFF0000u),
                                    z0 - __uint_as_float(ah2[2] << 16));
                al2[3] = cvt_bf16x2(z3 - __uint_as_float(ah2[3] & 0xFFFF0000u),
                                    z2 - __uint_as_float(ah2[3] << 16));
                mma_bf16(oacc[mt][0], ah2, &wh[0]);
                mma_bf16(oacc[mt][1], ah2, &wh[2]);
                mma_bf16(oacc[mt][0], al2, &wh[0]);
                mma_bf16(oacc[mt][1], al2, &wh[2]);
                mma_bf16(oacc[mt][0], ah2, &wl[0]);
                mma_bf16(oacc[mt][1], ah2, &wl[2]);
            }
        }

        // ---- stage 2 partial buffers by nw2 ----
#pragma unroll
        for (int mt = 0; mt < 2; ++mt) {
            float* obuf = smf + SB_OUT / 4 + nw2 * 5120;
            int p0 = mw2 * 32 + mt * 16 + r;
            float* s0 = obuf + p0 * 20;
            float* s1 = obuf + (p0 + 8) * 20;
            *(float2*)(s0 + 2 * q)     = make_float2(oacc[mt][0][0], oacc[mt][0][1]);
            *(float2*)(s0 + 8 + 2 * q) = make_float2(oacc[mt][1][0], oacc[mt][1][1]);
            *(float2*)(s1 + 2 * q)     = make_float2(oacc[mt][0][2], oacc[mt][0][3]);
            *(float2*)(s1 + 8 + 2 * q) = make_float2(oacc[mt][1][2], oacc[mt][1][3]);
        }
        __syncthreads();

        // ---- sum partials + coalesced store: 1024 float4, 2 passes ----
        {
            const float* o0 = smf + SB_OUT / 4;
#pragma unroll
            for (int t = 0; t < 2; ++t) {
                int i = tid + t * NTHREADS;
                int p = i >> 2, c4 = (i & 3) * 4;        // p in [0,256)
                int hr = p >> 7, w = p & 127;
                float4 v0 = *(const float4*)(o0 + p * 20 + c4);
                float4 v1 = *(const float4*)(o0 + 5120 + p * 20 + c4);
                float4 v = make_float4(v0.x + v1.x, v0.y + v1.y,
                                       v0.z + v1.z, v0.w + v1.w);
                long off = ((long)b << 18) + ((long)w << 11) +
                           ((long)(h0 + hr) << 4) + c4;
                *(float4*)(out + off) = v;
            }
        }
    }
}

extern "C" void kernel_launch(void* const* d_in, const int* in_sizes, int n_in,
                              void* d_out, int out_size) {
    const float* x  = (const float*)d_in[0];
    const float* Wx = (const float*)d_in[1];
    const float* bx = (const float*)d_in[2];
    const float* Wy = (const float*)d_in[3];
    const float* by = (const float*)d_in[4];
    const float* W1 = (const float*)d_in[5];
    const float* b1 = (const float*)d_in[6];
    const float* W2 = (const float*)d_in[7];
    const float* b2 = (const float*)d_in[8];
    float* out = (float*)d_out;

    prep_kernel<<<4096, 256>>>(x, Wx, Wy, W1, b1, bx, by, W2);

    cudaFuncSetAttribute(nca_mma_kernel,
                         cudaFuncAttributeMaxDynamicSharedMemorySize, SMEM_BYTES);
    nca_mma_kernel<<<NBLOCKS, NTHREADS, SMEM_BYTES>>>(b2, out);
}